// round 1
// baseline (speedup 1.0000x reference)
#include <cuda_runtime.h>
#include <math.h>

// Problem constants
#define SEQ     8192
#define BATCH   2
#define MTOT    (BATCH * SEQ)   // 16384
#define HIDDEN  768
#define KV      256
#define DMAX    7               // convolution half-width (e(d>=2) ~ 0 anyway)

// Scratch (static __device__ — no runtime allocation allowed)
__device__ float g_e[DMAX + 1];
__device__ __align__(16) float g_v[MTOT * KV];
__device__ __align__(16) float g_a[MTOT * KV];

// ---------------------------------------------------------------------------
// Kernel 0: exact softmax convolution coefficients
// w(d) = sum_{j=0}^{383} cos(d * 10000^(-j/384)),  e(d) = exp(w(d) - 384)
// ---------------------------------------------------------------------------
__global__ void coeff_kernel() {
    int d = threadIdx.x;
    if (d > DMAX) return;
    double s = 0.0;
    const double c = -log(10000.0) / 384.0;
    for (int j = 0; j < 384; ++j) {
        double f = exp(c * (double)j);
        s += cos((double)d * f);
    }
    g_e[d] = (float)exp(s - 384.0);   // w(0) == 384 exactly
}

// ---------------------------------------------------------------------------
// f32x2 packed math helpers (full-rate fp32 FMA path on sm_103a)
// ---------------------------------------------------------------------------
__device__ __forceinline__ unsigned long long pack2(float x, float y) {
    unsigned long long r;
    asm("mov.b64 %0, {%1, %2};" : "=l"(r) : "f"(x), "f"(y));
    return r;
}
__device__ __forceinline__ unsigned long long fma2(unsigned long long a,
                                                   unsigned long long b,
                                                   unsigned long long c) {
    unsigned long long d;
    asm("fma.rn.f32x2 %0, %1, %2, %3;" : "=l"(d) : "l"(a), "l"(b), "l"(c));
    return d;
}

// ---------------------------------------------------------------------------
// SGEMM (NT): C[m,n] = sum_k A[m*K+k] * B[n*K+k]
// A: [M,K] row-major, B: [N,K] row-major, C: [M,N] row-major.
// 128x128 block tile, BK=16, 256 threads, 8x8 per-thread tile, f32x2 inner.
// All dims are multiples of tile sizes here (no bounds checks).
// ---------------------------------------------------------------------------
__global__ __launch_bounds__(256) void sgemm_nt(
    const float* __restrict__ A, const float* __restrict__ B,
    float* __restrict__ C, int M, int N, int K)
{
    const int BM = 128, BN = 128, BK = 16;
    __shared__ float As[BK][BM];
    __shared__ float Bs[BK][BN];

    const int t  = threadIdx.x;
    const int bm = blockIdx.y * BM;
    const int bn = blockIdx.x * BN;

    const int lr = t >> 1;           // tile row this thread loads (0..127)
    const int lc = (t & 1) * 8;      // k offset within tile (0 or 8)

    const int ty = t >> 4;           // m-group (0..15)
    const int tx = t & 15;           // n-group (0..15)

    unsigned long long acc[8][4];
#pragma unroll
    for (int i = 0; i < 8; ++i)
#pragma unroll
        for (int j = 0; j < 4; ++j) acc[i][j] = 0ULL;

    for (int kt = 0; kt < K; kt += BK) {
        // global -> regs (coalesced-ish 32B per thread, rows of K-major data)
        const float4* ap = reinterpret_cast<const float4*>(
            A + (size_t)(bm + lr) * K + kt + lc);
        float4 a0 = ap[0], a1 = ap[1];
        const float4* bp = reinterpret_cast<const float4*>(
            B + (size_t)(bn + lr) * K + kt + lc);
        float4 b0 = bp[0], b1 = bp[1];

        __syncthreads();             // previous tile fully consumed
        As[lc + 0][lr] = a0.x; As[lc + 1][lr] = a0.y;
        As[lc + 2][lr] = a0.z; As[lc + 3][lr] = a0.w;
        As[lc + 4][lr] = a1.x; As[lc + 5][lr] = a1.y;
        As[lc + 6][lr] = a1.z; As[lc + 7][lr] = a1.w;
        Bs[lc + 0][lr] = b0.x; Bs[lc + 1][lr] = b0.y;
        Bs[lc + 2][lr] = b0.z; Bs[lc + 3][lr] = b0.w;
        Bs[lc + 4][lr] = b1.x; Bs[lc + 5][lr] = b1.y;
        Bs[lc + 6][lr] = b1.z; Bs[lc + 7][lr] = b1.w;
        __syncthreads();

#pragma unroll
        for (int k = 0; k < BK; ++k) {
            float a[8];
            *reinterpret_cast<float4*>(&a[0]) =
                *reinterpret_cast<const float4*>(&As[k][ty * 8]);
            *reinterpret_cast<float4*>(&a[4]) =
                *reinterpret_cast<const float4*>(&As[k][ty * 8 + 4]);
            unsigned long long b2[4];
            const unsigned long long* bq =
                reinterpret_cast<const unsigned long long*>(&Bs[k][tx * 8]);
            b2[0] = bq[0]; b2[1] = bq[1]; b2[2] = bq[2]; b2[3] = bq[3];
#pragma unroll
            for (int i = 0; i < 8; ++i) {
                unsigned long long a2 = pack2(a[i], a[i]);
#pragma unroll
                for (int j = 0; j < 4; ++j)
                    acc[i][j] = fma2(a2, b2[j], acc[i][j]);
            }
        }
    }

    // epilogue: acc pairs are adjacent n-columns -> store as 8B words
#pragma unroll
    for (int i = 0; i < 8; ++i) {
        unsigned long long* cp = reinterpret_cast<unsigned long long*>(
            C + (size_t)(bm + ty * 8 + i) * N + bn + tx * 8);
#pragma unroll
        for (int j = 0; j < 4; ++j) cp[j] = acc[i][j];
    }
}

// ---------------------------------------------------------------------------
// Kernel 2: softmax as a tiny normalized symmetric convolution along seq
// a[m] = (sum_{|d|<=DMAX, valid} e(|d|) * v[m+d]) / Z(m), batch-aware bounds.
// ---------------------------------------------------------------------------
__global__ void smooth_kernel() {
    const int NC4 = KV / 4;
    int idx = blockIdx.x * blockDim.x + threadIdx.x;
    if (idx >= MTOT * NC4) return;
    int m = idx / NC4;
    int c = idx - m * NC4;
    int s = m & (SEQ - 1);

    const float4* vp = reinterpret_cast<const float4*>(g_v);
    float4 acc = vp[(size_t)m * NC4 + c];   // d = 0, e(0) = 1
    float z = 1.0f;
#pragma unroll
    for (int d = 1; d <= DMAX; ++d) {
        float e = g_e[d];
        if (s >= d) {
            float4 v = vp[(size_t)(m - d) * NC4 + c];
            acc.x += e * v.x; acc.y += e * v.y;
            acc.z += e * v.z; acc.w += e * v.w;
            z += e;
        }
        if (s + d < SEQ) {
            float4 v = vp[(size_t)(m + d) * NC4 + c];
            acc.x += e * v.x; acc.y += e * v.y;
            acc.z += e * v.z; acc.w += e * v.w;
            z += e;
        }
    }
    float inv = 1.0f / z;
    float4 o;
    o.x = acc.x * inv; o.y = acc.y * inv;
    o.z = acc.z * inv; o.w = acc.w * inv;
    reinterpret_cast<float4*>(g_a)[(size_t)m * NC4 + c] = o;
}

// ---------------------------------------------------------------------------
// Launch
// ---------------------------------------------------------------------------
extern "C" void kernel_launch(void* const* d_in, const int* in_sizes, int n_in,
                              void* d_out, int out_size) {
    const float* x  = (const float*)d_in[0];
    // d_in[1] = Wq, d_in[2] = Wk are dead in the reference (rope ignores input)
    const float* Wv = (const float*)d_in[3];
    const float* Wo = (const float*)d_in[4];
    float* out = (float*)d_out;

    float* v_buf;  cudaGetSymbolAddress((void**)&v_buf, g_v);
    float* a_buf;  cudaGetSymbolAddress((void**)&a_buf, g_a);

    // 0) exact convolution coefficients
    coeff_kernel<<<1, DMAX + 1>>>();

    // 1) v = x @ Wv^T : [16384,768] x [256,768] -> [16384,256]
    {
        dim3 grid(KV / 128, MTOT / 128);
        sgemm_nt<<<grid, 256>>>(x, Wv, v_buf, MTOT, KV, HIDDEN);
    }

    // 2) softmax(attn) @ v  ==  normalized 15-tap convolution of v
    {
        int n = MTOT * (KV / 4);
        smooth_kernel<<<(n + 255) / 256, 256>>>();
    }

    // 3) out = a @ Wo^T : [16384,256] x [768,256] -> [16384,768]
    {
        dim3 grid(HIDDEN / 128, MTOT / 128);
        sgemm_nt<<<grid, 256>>>(a_buf, Wo, out, MTOT, HIDDEN, KV);
    }
}

// round 2
// speedup vs baseline: 2.3621x; 2.3621x over previous
#include <cuda_runtime.h>
#include <math.h>

// Problem constants
#define SEQ     8192
#define BATCH   2
#define MTOT    (BATCH * SEQ)   // 16384
#define HIDDEN  768
#define KV      256
#define DMAX    7               // convolution half-width (e(d>=2) ~ 0 anyway)

// Scratch (static __device__ — no runtime allocation allowed)
__device__ float g_e[DMAX + 1];
__device__ __align__(16) float g_v[MTOT * KV];
__device__ __align__(16) float g_a[MTOT * KV];

// ---------------------------------------------------------------------------
// Kernel 0: softmax convolution coefficients, PARALLEL float version.
// w(d) = sum_{j=0}^{383} cos(d * 10000^(-j/384)),  e(d) = exp(w(d) - 384)
// 384 threads, each owns one frequency j; block-reduce per d.
// Float is ample: abs err in w ~2e-6 -> e(d) relative err ~2e-6, and the
// smooth kernel renormalizes by Z so common-mode error cancels.
// ---------------------------------------------------------------------------
__global__ void coeff_kernel() {
    __shared__ float warp_sum[12];   // 384 threads = 12 warps
    const int j = threadIdx.x;       // 0..383
    const int lane = j & 31, warp = j >> 5;
    const float c = -logf(10000.0f) / 384.0f;
    const float f = __expf(c * (float)j);

    for (int d = 0; d <= DMAX; ++d) {
        float val = cosf((float)d * f);
        // warp reduce
        #pragma unroll
        for (int o = 16; o; o >>= 1) val += __shfl_xor_sync(0xffffffffu, val, o);
        if (lane == 0) warp_sum[warp] = val;
        __syncthreads();
        if (j == 0) {
            float w = 0.f;
            #pragma unroll
            for (int i = 0; i < 12; ++i) w += warp_sum[i];
            g_e[d] = expf(w - 384.0f);
        }
        __syncthreads();
    }
}

// ---------------------------------------------------------------------------
// f32x2 packed math helpers (full-rate fp32 FMA path on sm_103a)
// ---------------------------------------------------------------------------
__device__ __forceinline__ unsigned long long pack2(float x, float y) {
    unsigned long long r;
    asm("mov.b64 %0, {%1, %2};" : "=l"(r) : "f"(x), "f"(y));
    return r;
}
__device__ __forceinline__ unsigned long long fma2(unsigned long long a,
                                                   unsigned long long b,
                                                   unsigned long long c) {
    unsigned long long d;
    asm("fma.rn.f32x2 %0, %1, %2, %3;" : "=l"(d) : "l"(a), "l"(b), "l"(c));
    return d;
}

// ---------------------------------------------------------------------------
// SGEMM (NT): C[m,n] = sum_k A[m*K+k] * B[n*K+k]
// A: [M,K] row-major, B: [N,K] row-major, C: [M,N] row-major.
// 128x128 block tile, BK=16, 256 threads, 8x8 per-thread tile, f32x2 inner.
// Software-pipelined: next tile's global loads issue BEFORE the compute of
// the current tile, hiding DRAM/L2 latency behind 2048 FFMA2s.
// All dims are multiples of tile sizes here (no bounds checks).
// ---------------------------------------------------------------------------
__global__ __launch_bounds__(256) void sgemm_nt(
    const float* __restrict__ A, const float* __restrict__ B,
    float* __restrict__ C, int M, int N, int K)
{
    const int BM = 128, BN = 128, BK = 16;
    __shared__ float As[BK][BM];
    __shared__ float Bs[BK][BN];

    const int t  = threadIdx.x;
    const int bm = blockIdx.y * BM;
    const int bn = blockIdx.x * BN;

    const int lr = t >> 1;           // tile row this thread loads (0..127)
    const int lc = (t & 1) * 8;      // k offset within tile (0 or 8)

    const int ty = t >> 4;           // m-group (0..15)
    const int tx = t & 15;           // n-group (0..15)

    const float* aBase = A + (size_t)(bm + lr) * K + lc;
    const float* bBase = B + (size_t)(bn + lr) * K + lc;

    unsigned long long acc[8][4];
#pragma unroll
    for (int i = 0; i < 8; ++i)
#pragma unroll
        for (int j = 0; j < 4; ++j) acc[i][j] = 0ULL;

    // prefetch tile 0
    float4 a0 = reinterpret_cast<const float4*>(aBase)[0];
    float4 a1 = reinterpret_cast<const float4*>(aBase)[1];
    float4 b0 = reinterpret_cast<const float4*>(bBase)[0];
    float4 b1 = reinterpret_cast<const float4*>(bBase)[1];

    for (int kt = 0; kt < K; kt += BK) {
        __syncthreads();             // previous tile fully consumed
        As[lc + 0][lr] = a0.x; As[lc + 1][lr] = a0.y;
        As[lc + 2][lr] = a0.z; As[lc + 3][lr] = a0.w;
        As[lc + 4][lr] = a1.x; As[lc + 5][lr] = a1.y;
        As[lc + 6][lr] = a1.z; As[lc + 7][lr] = a1.w;
        Bs[lc + 0][lr] = b0.x; Bs[lc + 1][lr] = b0.y;
        Bs[lc + 2][lr] = b0.z; Bs[lc + 3][lr] = b0.w;
        Bs[lc + 4][lr] = b1.x; Bs[lc + 5][lr] = b1.y;
        Bs[lc + 6][lr] = b1.z; Bs[lc + 7][lr] = b1.w;
        __syncthreads();

        // issue next tile's global loads NOW; latency hides behind compute
        if (kt + BK < K) {
            const float* ap = aBase + kt + BK;
            const float* bp = bBase + kt + BK;
            a0 = reinterpret_cast<const float4*>(ap)[0];
            a1 = reinterpret_cast<const float4*>(ap)[1];
            b0 = reinterpret_cast<const float4*>(bp)[0];
            b1 = reinterpret_cast<const float4*>(bp)[1];
        }

#pragma unroll
        for (int k = 0; k < BK; ++k) {
            float a[8];
            *reinterpret_cast<float4*>(&a[0]) =
                *reinterpret_cast<const float4*>(&As[k][ty * 8]);
            *reinterpret_cast<float4*>(&a[4]) =
                *reinterpret_cast<const float4*>(&As[k][ty * 8 + 4]);
            unsigned long long b2[4];
            const unsigned long long* bq =
                reinterpret_cast<const unsigned long long*>(&Bs[k][tx * 8]);
            b2[0] = bq[0]; b2[1] = bq[1]; b2[2] = bq[2]; b2[3] = bq[3];
#pragma unroll
            for (int i = 0; i < 8; ++i) {
                unsigned long long a2 = pack2(a[i], a[i]);
#pragma unroll
                for (int j = 0; j < 4; ++j)
                    acc[i][j] = fma2(a2, b2[j], acc[i][j]);
            }
        }
    }

    // epilogue: acc pairs are adjacent n-columns -> store as 8B words
#pragma unroll
    for (int i = 0; i < 8; ++i) {
        unsigned long long* cp = reinterpret_cast<unsigned long long*>(
            C + (size_t)(bm + ty * 8 + i) * N + bn + tx * 8);
#pragma unroll
        for (int j = 0; j < 4; ++j) cp[j] = acc[i][j];
    }
}

// ---------------------------------------------------------------------------
// Kernel 2: softmax as a tiny normalized symmetric convolution along seq
// a[m] = (sum_{|d|<=DMAX, valid} e(|d|) * v[m+d]) / Z(m), batch-aware bounds.
// ---------------------------------------------------------------------------
__global__ void smooth_kernel() {
    const int NC4 = KV / 4;
    int idx = blockIdx.x * blockDim.x + threadIdx.x;
    if (idx >= MTOT * NC4) return;
    int m = idx / NC4;
    int c = idx - m * NC4;
    int s = m & (SEQ - 1);

    const float4* vp = reinterpret_cast<const float4*>(g_v);
    float4 acc = vp[(size_t)m * NC4 + c];   // d = 0, e(0) = 1
    float z = 1.0f;
#pragma unroll
    for (int d = 1; d <= DMAX; ++d) {
        float e = g_e[d];
        if (s >= d) {
            float4 v = vp[(size_t)(m - d) * NC4 + c];
            acc.x += e * v.x; acc.y += e * v.y;
            acc.z += e * v.z; acc.w += e * v.w;
            z += e;
        }
        if (s + d < SEQ) {
            float4 v = vp[(size_t)(m + d) * NC4 + c];
            acc.x += e * v.x; acc.y += e * v.y;
            acc.z += e * v.z; acc.w += e * v.w;
            z += e;
        }
    }
    float inv = 1.0f / z;
    float4 o;
    o.x = acc.x * inv; o.y = acc.y * inv;
    o.z = acc.z * inv; o.w = acc.w * inv;
    reinterpret_cast<float4*>(g_a)[(size_t)m * NC4 + c] = o;
}

// ---------------------------------------------------------------------------
// Launch
// ---------------------------------------------------------------------------
extern "C" void kernel_launch(void* const* d_in, const int* in_sizes, int n_in,
                              void* d_out, int out_size) {
    const float* x  = (const float*)d_in[0];
    // d_in[1] = Wq, d_in[2] = Wk are dead in the reference (rope ignores input)
    const float* Wv = (const float*)d_in[3];
    const float* Wo = (const float*)d_in[4];
    float* out = (float*)d_out;

    float* v_buf;  cudaGetSymbolAddress((void**)&v_buf, g_v);
    float* a_buf;  cudaGetSymbolAddress((void**)&a_buf, g_a);

    // 0) convolution coefficients (parallel, float)
    coeff_kernel<<<1, 384>>>();

    // 1) v = x @ Wv^T : [16384,768] x [256,768] -> [16384,256]
    {
        dim3 grid(KV / 128, MTOT / 128);
        sgemm_nt<<<grid, 256>>>(x, Wv, v_buf, MTOT, KV, HIDDEN);
    }

    // 2) softmax(attn) @ v  ==  normalized 15-tap convolution of v
    {
        int n = MTOT * (KV / 4);
        smooth_kernel<<<(n + 255) / 256, 256>>>();
    }

    // 3) out = a @ Wo^T : [16384,256] x [768,256] -> [16384,768]
    {
        dim3 grid(HIDDEN / 128, MTOT / 128);
        sgemm_nt<<<grid, 256>>>(a_buf, Wo, out, MTOT, HIDDEN, KV);
    }
}

// round 4
// speedup vs baseline: 4.2134x; 1.7838x over previous
#include <cuda_runtime.h>
#include <cuda_bf16.h>
#include <math.h>
#include <stdint.h>

// Problem constants
#define SEQ     8192
#define BATCH   2
#define MTOT    (BATCH * SEQ)   // 16384
#define HIDDEN  768
#define KV      256
#define DMAX    7

// Scratch (static __device__ — no runtime allocation allowed)
__device__ float g_e[DMAX + 1];
__device__ __align__(16) float g_v[MTOT * KV];
__device__ __align__(16) float g_a[MTOT * KV];

// ---------------------------------------------------------------------------
// helpers
// ---------------------------------------------------------------------------
__device__ __forceinline__ uint32_t smem_u32(const void* p) {
    uint32_t a;
    asm("{ .reg .u64 t; cvta.to.shared.u64 t, %1; cvt.u32.u64 %0, t; }"
        : "=r"(a) : "l"(p));
    return a;
}

// split fp32 pair (x at lower k, y at higher k) into packed bf16x2 hi & lo
__device__ __forceinline__ void cvt_split(float x, float y,
                                          uint32_t& hi, uint32_t& lo) {
    uint32_t xb = __float_as_uint(x), yb = __float_as_uint(y);
    asm("prmt.b32 %0, %1, %2, 0x7632;" : "=r"(hi) : "r"(xb), "r"(yb));
    float xh = __uint_as_float(xb & 0xFFFF0000u);
    float yh = __uint_as_float(yb & 0xFFFF0000u);
    float xl = x - xh, yl = y - yh;
    asm("cvt.rn.bf16x2.f32 %0, %1, %2;" : "=r"(lo) : "f"(yl), "f"(xl));
}

__device__ __forceinline__ void ldsm4(uint32_t* r, uint32_t addr) {
    asm volatile("ldmatrix.sync.aligned.m8n8.x4.shared.b16 {%0,%1,%2,%3}, [%4];"
        : "=r"(r[0]), "=r"(r[1]), "=r"(r[2]), "=r"(r[3]) : "r"(addr));
}

__device__ __forceinline__ void mma16816(float* d, const uint32_t* a,
                                         const uint32_t* b) {
    asm volatile(
        "mma.sync.aligned.m16n8k16.row.col.f32.bf16.bf16.f32 "
        "{%0,%1,%2,%3}, {%4,%5,%6,%7}, {%8,%9}, {%0,%1,%2,%3};"
        : "+f"(d[0]), "+f"(d[1]), "+f"(d[2]), "+f"(d[3])
        : "r"(a[0]), "r"(a[1]), "r"(a[2]), "r"(a[3]), "r"(b[0]), "r"(b[1]));
}

// conflict-free XOR swizzle inside a 128-row x 64-byte (32 bf16) tile layer
__device__ __forceinline__ uint32_t swz(uint32_t base, int row, int kg) {
    uint32_t g = (uint32_t)(kg ^ (row & 3) ^ ((row & 4) >> 1));
    return base + (uint32_t)row * 64u + (g << 4);
}

// ---------------------------------------------------------------------------
// Split-bf16 tensor-core GEMM (NT): C[m,n] = sum_k A[m*K+k] * B[n*K+k]
// fp32 in/out. 3-term bf16 split for fp32-grade accuracy.
// 128x128 CTA tile, BK=32, 8 warps (2x4), warp tile 64x32 via m16n8k16 MMAs.
// Double-buffered SMEM (2 stages x 32KB), one __syncthreads per chunk.
// M, N multiples of 128; K multiple of 32.
// ---------------------------------------------------------------------------
__global__ __launch_bounds__(256, 1) void gemm_mma(
    const float* __restrict__ A, const float* __restrict__ B,
    float* __restrict__ C, int M, int N, int K)
{
    extern __shared__ char dynsmem[];
    const uint32_t sb = (smem_u32(dynsmem) + 127u) & ~127u;
    // per stage: Ah(8K) Al(8K) Bh(8K) Bl(8K)
    const uint32_t STG = 32768;

    const int tid  = threadIdx.x;
    const int wid  = tid >> 5;
    const int lane = tid & 31;
    const int bm   = blockIdx.y * 128;
    const int bn   = blockIdx.x * 128;
    const int NC   = K >> 5;

    const int warpM = (wid >> 2) * 64;   // 0 or 64
    const int warpN = (wid & 3) * 32;    // 0..96

    // loader mapping: thread -> (row 0..127, k-half 0..1 of the 32-wide chunk)
    const int r = tid >> 1;
    const int h = tid & 1;
    const float* aRow = A + (size_t)(bm + r) * K + h * 16;
    const float* bRow = B + (size_t)(bn + r) * K + h * 16;

    float acc[4][4][4];
#pragma unroll
    for (int i = 0; i < 4; ++i)
#pragma unroll
        for (int j = 0; j < 4; ++j)
#pragma unroll
            for (int q = 0; q < 4; ++q) acc[i][j][q] = 0.f;

    float4   av[4], bv[4];
    uint32_t cAh[8], cAl[8], cBh[8], cBl[8];

#define CONVERT_ALL()                                                     \
    do {                                                                  \
        _Pragma("unroll")                                                 \
        for (int i = 0; i < 4; ++i) {                                     \
            cvt_split(av[i].x, av[i].y, cAh[2*i],   cAl[2*i]);            \
            cvt_split(av[i].z, av[i].w, cAh[2*i+1], cAl[2*i+1]);          \
            cvt_split(bv[i].x, bv[i].y, cBh[2*i],   cBl[2*i]);            \
            cvt_split(bv[i].z, bv[i].w, cBh[2*i+1], cBl[2*i+1]);          \
        }                                                                 \
    } while (0)

#define STS_ALL(stage)                                                    \
    do {                                                                  \
        uint32_t base = sb + (uint32_t)(stage) * STG;                     \
        uint32_t g0 = h * 2, g1 = h * 2 + 1;                              \
        asm volatile("st.shared.v4.b32 [%0], {%1,%2,%3,%4};" ::           \
            "r"(swz(base, r, g0)), "r"(cAh[0]), "r"(cAh[1]),              \
            "r"(cAh[2]), "r"(cAh[3]) : "memory");                         \
        asm volatile("st.shared.v4.b32 [%0], {%1,%2,%3,%4};" ::           \
            "r"(swz(base, r, g1)), "r"(cAh[4]), "r"(cAh[5]),              \
            "r"(cAh[6]), "r"(cAh[7]) : "memory");                         \
        asm volatile("st.shared.v4.b32 [%0], {%1,%2,%3,%4};" ::           \
            "r"(swz(base + 8192, r, g0)), "r"(cAl[0]), "r"(cAl[1]),       \
            "r"(cAl[2]), "r"(cAl[3]) : "memory");                         \
        asm volatile("st.shared.v4.b32 [%0], {%1,%2,%3,%4};" ::           \
            "r"(swz(base + 8192, r, g1)), "r"(cAl[4]), "r"(cAl[5]),       \
            "r"(cAl[6]), "r"(cAl[7]) : "memory");                         \
        asm volatile("st.shared.v4.b32 [%0], {%1,%2,%3,%4};" ::           \
            "r"(swz(base + 16384, r, g0)), "r"(cBh[0]), "r"(cBh[1]),      \
            "r"(cBh[2]), "r"(cBh[3]) : "memory");                         \
        asm volatile("st.shared.v4.b32 [%0], {%1,%2,%3,%4};" ::           \
            "r"(swz(base + 16384, r, g1)), "r"(cBh[4]), "r"(cBh[5]),      \
            "r"(cBh[6]), "r"(cBh[7]) : "memory");                         \
        asm volatile("st.shared.v4.b32 [%0], {%1,%2,%3,%4};" ::           \
            "r"(swz(base + 24576, r, g0)), "r"(cBl[0]), "r"(cBl[1]),      \
            "r"(cBl[2]), "r"(cBl[3]) : "memory");                         \
        asm volatile("st.shared.v4.b32 [%0], {%1,%2,%3,%4};" ::           \
            "r"(swz(base + 24576, r, g1)), "r"(cBl[4]), "r"(cBl[5]),      \
            "r"(cBl[6]), "r"(cBl[7]) : "memory");                         \
    } while (0)

    // prologue: stage chunk 0
#pragma unroll
    for (int i = 0; i < 4; ++i) av[i] = reinterpret_cast<const float4*>(aRow)[i];
#pragma unroll
    for (int i = 0; i < 4; ++i) bv[i] = reinterpret_cast<const float4*>(bRow)[i];
    CONVERT_ALL();
    STS_ALL(0);
    __syncthreads();

    // ldmatrix lane address components (A: 16 rows x 2 kgroups; B: 8/8 split)
    const int laRow = warpM + (lane & 15);
    const int laKg  = lane >> 4;
    const int lbRow = warpN + (lane & 7) + ((lane & 16) >> 1);
    const int lbKg  = (lane >> 3) & 1;

    for (int c = 0; c < NC; ++c) {
        // issue next chunk's global loads NOW; consumed after the MMA block
        if (c + 1 < NC) {
            const float* ap = aRow + (c + 1) * 32;
            const float* bp = bRow + (c + 1) * 32;
#pragma unroll
            for (int i = 0; i < 4; ++i) av[i] = reinterpret_cast<const float4*>(ap)[i];
#pragma unroll
            for (int i = 0; i < 4; ++i) bv[i] = reinterpret_cast<const float4*>(bp)[i];
        }

        const uint32_t base = sb + (uint32_t)(c & 1) * STG;
        const uint32_t bAh = base, bAl = base + 8192;
        const uint32_t bBh = base + 16384, bBl = base + 24576;

#pragma unroll
        for (int ks = 0; ks < 2; ++ks) {
            uint32_t ah[4][4], al[4][4], bh[2][4], bl[2][4];
#pragma unroll
            for (int mt = 0; mt < 4; ++mt) {
                ldsm4(ah[mt], swz(bAh, laRow + mt * 16, ks * 2 + laKg));
                ldsm4(al[mt], swz(bAl, laRow + mt * 16, ks * 2 + laKg));
            }
#pragma unroll
            for (int j = 0; j < 2; ++j) {
                ldsm4(bh[j], swz(bBh, lbRow + j * 16, ks * 2 + lbKg));
                ldsm4(bl[j], swz(bBl, lbRow + j * 16, ks * 2 + lbKg));
            }
#pragma unroll
            for (int mt = 0; mt < 4; ++mt) {
#pragma unroll
                for (int nt = 0; nt < 4; ++nt) {
                    const uint32_t* bph = &bh[nt >> 1][(nt & 1) * 2];
                    const uint32_t* bpl = &bl[nt >> 1][(nt & 1) * 2];
                    mma16816(acc[mt][nt], ah[mt], bph);
                    mma16816(acc[mt][nt], ah[mt], bpl);
                    mma16816(acc[mt][nt], al[mt], bph);
                }
            }
        }

        if (c + 1 < NC) {
            CONVERT_ALL();
            STS_ALL((c + 1) & 1);
        }
        __syncthreads();
    }

    // epilogue: direct global stores (8B per lane per sub-tile row)
#pragma unroll
    for (int mt = 0; mt < 4; ++mt) {
#pragma unroll
        for (int nt = 0; nt < 4; ++nt) {
            int row = bm + warpM + mt * 16 + (lane >> 2);
            int col = bn + warpN + nt * 8 + (lane & 3) * 2;
            float2 v0 = make_float2(acc[mt][nt][0], acc[mt][nt][1]);
            float2 v1 = make_float2(acc[mt][nt][2], acc[mt][nt][3]);
            *reinterpret_cast<float2*>(C + (size_t)row * N + col) = v0;
            *reinterpret_cast<float2*>(C + (size_t)(row + 8) * N + col) = v1;
        }
    }
#undef CONVERT_ALL
#undef STS_ALL
}

// ---------------------------------------------------------------------------
// Kernel 0: softmax convolution coefficients (parallel float)
// ---------------------------------------------------------------------------
__global__ void coeff_kernel() {
    __shared__ float warp_sum[12];
    const int j = threadIdx.x;
    const int lane = j & 31, warp = j >> 5;
    const float c = -logf(10000.0f) / 384.0f;
    const float f = __expf(c * (float)j);
    for (int d = 0; d <= DMAX; ++d) {
        float val = cosf((float)d * f);
#pragma unroll
        for (int o = 16; o; o >>= 1) val += __shfl_xor_sync(0xffffffffu, val, o);
        if (lane == 0) warp_sum[warp] = val;
        __syncthreads();
        if (j == 0) {
            float w = 0.f;
#pragma unroll
            for (int i = 0; i < 12; ++i) w += warp_sum[i];
            g_e[d] = expf(w - 384.0f);
        }
        __syncthreads();
    }
}

// ---------------------------------------------------------------------------
// Kernel 2: softmax == normalized 15-tap convolution along seq
// ---------------------------------------------------------------------------
__global__ void smooth_kernel() {
    const int NC4 = KV / 4;
    int idx = blockIdx.x * blockDim.x + threadIdx.x;
    if (idx >= MTOT * NC4) return;
    int m = idx / NC4;
    int c = idx - m * NC4;
    int s = m & (SEQ - 1);

    const float4* vp = reinterpret_cast<const float4*>(g_v);
    float4 acc = vp[(size_t)m * NC4 + c];
    float z = 1.0f;
#pragma unroll
    for (int d = 1; d <= DMAX; ++d) {
        float e = g_e[d];
        if (s >= d) {
            float4 v = vp[(size_t)(m - d) * NC4 + c];
            acc.x += e * v.x; acc.y += e * v.y;
            acc.z += e * v.z; acc.w += e * v.w;
            z += e;
        }
        if (s + d < SEQ) {
            float4 v = vp[(size_t)(m + d) * NC4 + c];
            acc.x += e * v.x; acc.y += e * v.y;
            acc.z += e * v.z; acc.w += e * v.w;
            z += e;
        }
    }
    float inv = 1.0f / z;
    float4 o;
    o.x = acc.x * inv; o.y = acc.y * inv;
    o.z = acc.z * inv; o.w = acc.w * inv;
    reinterpret_cast<float4*>(g_a)[(size_t)m * NC4 + c] = o;
}

// ---------------------------------------------------------------------------
// Launch
// ---------------------------------------------------------------------------
extern "C" void kernel_launch(void* const* d_in, const int* in_sizes, int n_in,
                              void* d_out, int out_size) {
    const float* x  = (const float*)d_in[0];
    // d_in[1] = Wq, d_in[2] = Wk are dead (rope ignores its input)
    const float* Wv = (const float*)d_in[3];
    const float* Wo = (const float*)d_in[4];
    float* out = (float*)d_out;

    float* v_buf;  cudaGetSymbolAddress((void**)&v_buf, g_v);
    float* a_buf;  cudaGetSymbolAddress((void**)&a_buf, g_a);

    const int SMEM_BYTES = 65536 + 128;
    cudaFuncSetAttribute(gemm_mma, cudaFuncAttributeMaxDynamicSharedMemorySize,
                         SMEM_BYTES);

    coeff_kernel<<<1, 384>>>();

    // 1) v = x @ Wv^T : [16384,768] x [256,768]
    gemm_mma<<<dim3(KV / 128, MTOT / 128), 256, SMEM_BYTES>>>(
        x, Wv, v_buf, MTOT, KV, HIDDEN);

    // 2) softmax(attn) @ v == normalized 15-tap convolution
    {
        int n = MTOT * (KV / 4);
        smooth_kernel<<<(n + 255) / 256, 256>>>();
    }

    // 3) out = a @ Wo^T : [16384,256] x [768,256]
    gemm_mma<<<dim3(HIDDEN / 128, MTOT / 128), 256, SMEM_BYTES>>>(
        a_buf, Wo, out, MTOT, HIDDEN, KV);
}

// round 5
// speedup vs baseline: 4.4514x; 1.0565x over previous
#include <cuda_runtime.h>
#include <cuda_bf16.h>
#include <math.h>
#include <stdint.h>

// Problem constants
#define SEQ     8192
#define BATCH   2
#define MTOT    (BATCH * SEQ)   // 16384
#define HIDDEN  768
#define KV      256
#define DMAX    7

// Scratch (static __device__ — no runtime allocation allowed)
__device__ float g_e[DMAX + 1];
__device__ __align__(16) float g_v[MTOT * KV];
__device__ __align__(16) float g_a[MTOT * KV];

// ---------------------------------------------------------------------------
// helpers
// ---------------------------------------------------------------------------
__device__ __forceinline__ uint32_t smem_u32(const void* p) {
    uint32_t a;
    asm("{ .reg .u64 t; cvta.to.shared.u64 t, %1; cvt.u32.u64 %0, t; }"
        : "=r"(a) : "l"(p));
    return a;
}

// split fp32 pair (x at lower k, y at higher k) into packed bf16x2 hi & lo
__device__ __forceinline__ void cvt_split(float x, float y,
                                          uint32_t& hi, uint32_t& lo) {
    uint32_t xb = __float_as_uint(x), yb = __float_as_uint(y);
    asm("prmt.b32 %0, %1, %2, 0x7632;" : "=r"(hi) : "r"(xb), "r"(yb));
    float xh = __uint_as_float(xb & 0xFFFF0000u);
    float yh = __uint_as_float(yb & 0xFFFF0000u);
    float xl = x - xh, yl = y - yh;
    asm("cvt.rn.bf16x2.f32 %0, %1, %2;" : "=r"(lo) : "f"(yl), "f"(xl));
}

__device__ __forceinline__ void ldsm4(uint32_t* r, uint32_t addr) {
    asm volatile("ldmatrix.sync.aligned.m8n8.x4.shared.b16 {%0,%1,%2,%3}, [%4];"
        : "=r"(r[0]), "=r"(r[1]), "=r"(r[2]), "=r"(r[3]) : "r"(addr));
}

__device__ __forceinline__ void mma16816(float* d, const uint32_t* a,
                                         const uint32_t* b) {
    asm volatile(
        "mma.sync.aligned.m16n8k16.row.col.f32.bf16.bf16.f32 "
        "{%0,%1,%2,%3}, {%4,%5,%6,%7}, {%8,%9}, {%0,%1,%2,%3};"
        : "+f"(d[0]), "+f"(d[1]), "+f"(d[2]), "+f"(d[3])
        : "r"(a[0]), "r"(a[1]), "r"(a[2]), "r"(a[3]), "r"(b[0]), "r"(b[1]));
}

// conflict-free XOR swizzle inside a 128-row x 64-byte (32 bf16) tile layer
__device__ __forceinline__ uint32_t swz(uint32_t base, int row, int kg) {
    uint32_t g = (uint32_t)(kg ^ (row & 3) ^ ((row & 4) >> 1));
    return base + (uint32_t)row * 64u + (g << 4);
}

// convert 16 consecutive fp32 k-values (4 float4) and store hi/lo bf16 layers
__device__ __forceinline__ void cvt_sts(const float4* v, uint32_t baseHi,
                                        uint32_t baseLo, int r, int g0) {
    uint32_t hi[8], lo[8];
#pragma unroll
    for (int i = 0; i < 4; ++i) {
        cvt_split(v[i].x, v[i].y, hi[2*i],   lo[2*i]);
        cvt_split(v[i].z, v[i].w, hi[2*i+1], lo[2*i+1]);
    }
    asm volatile("st.shared.v4.b32 [%0], {%1,%2,%3,%4};" ::
        "r"(swz(baseHi, r, g0)), "r"(hi[0]), "r"(hi[1]), "r"(hi[2]), "r"(hi[3])
        : "memory");
    asm volatile("st.shared.v4.b32 [%0], {%1,%2,%3,%4};" ::
        "r"(swz(baseHi, r, g0 + 1)), "r"(hi[4]), "r"(hi[5]), "r"(hi[6]), "r"(hi[7])
        : "memory");
    asm volatile("st.shared.v4.b32 [%0], {%1,%2,%3,%4};" ::
        "r"(swz(baseLo, r, g0)), "r"(lo[0]), "r"(lo[1]), "r"(lo[2]), "r"(lo[3])
        : "memory");
    asm volatile("st.shared.v4.b32 [%0], {%1,%2,%3,%4};" ::
        "r"(swz(baseLo, r, g0 + 1)), "r"(lo[4]), "r"(lo[5]), "r"(lo[6]), "r"(lo[7])
        : "memory");
}

// ---------------------------------------------------------------------------
// Split-bf16 tensor-core GEMM (NT): C[m,n] = sum_k A[m*K+k] * B[n*K+k]
// fp32 in/out. 3-term bf16 split (hi*hi + hi*lo + lo*hi) for fp32-grade
// accuracy. 128x128 CTA tile, BK=32, 8 warps (2x4), warp tile 64x32.
// Double-buffered SMEM, one __syncthreads per chunk, register-lean phased
// prefetch (A then B) so 2 CTAs fit per SM.
// ---------------------------------------------------------------------------
__global__ __launch_bounds__(256, 2) void gemm_mma(
    const float* __restrict__ A, const float* __restrict__ B,
    float* __restrict__ C, int M, int N, int K)
{
    extern __shared__ char dynsmem[];
    const uint32_t sb = (smem_u32(dynsmem) + 127u) & ~127u;
    const uint32_t STG = 32768;   // per stage: Ah(8K) Al(8K) Bh(8K) Bl(8K)

    const int tid  = threadIdx.x;
    const int wid  = tid >> 5;
    const int lane = tid & 31;
    const int bm   = blockIdx.y * 128;
    const int bn   = blockIdx.x * 128;
    const int NC   = K >> 5;

    const int warpM = (wid >> 2) * 64;   // 0 or 64
    const int warpN = (wid & 3) * 32;    // 0..96

    // loader mapping: thread -> (row 0..127, k-half 0..1 of the 32-wide chunk)
    const int r = tid >> 1;
    const int h = tid & 1;
    const int g0 = h * 2;
    const float* aRow = A + (size_t)(bm + r) * K + h * 16;
    const float* bRow = B + (size_t)(bn + r) * K + h * 16;

    float acc[4][4][4];
#pragma unroll
    for (int i = 0; i < 4; ++i)
#pragma unroll
        for (int j = 0; j < 4; ++j)
#pragma unroll
            for (int q = 0; q < 4; ++q) acc[i][j][q] = 0.f;

    float4 stage4[4];

    // prologue: stage chunk 0
#pragma unroll
    for (int i = 0; i < 4; ++i) stage4[i] = reinterpret_cast<const float4*>(aRow)[i];
    cvt_sts(stage4, sb, sb + 8192, r, g0);
#pragma unroll
    for (int i = 0; i < 4; ++i) stage4[i] = reinterpret_cast<const float4*>(bRow)[i];
    cvt_sts(stage4, sb + 16384, sb + 24576, r, g0);
    __syncthreads();

    // ldmatrix lane address components (A: 16 rows x 2 kgroups; B: 8/8 split)
    const int laRow = warpM + (lane & 15);
    const int laKg  = lane >> 4;
    const int lbRow = warpN + (lane & 7) + ((lane & 16) >> 1);
    const int lbKg  = (lane >> 3) & 1;

    for (int c = 0; c < NC; ++c) {
        const uint32_t base = sb + (uint32_t)(c & 1) * STG;
        const uint32_t nbase = sb + (uint32_t)((c + 1) & 1) * STG;
        const uint32_t bAh = base, bAl = base + 8192;
        const uint32_t bBh = base + 16384, bBl = base + 24576;
        const bool more = (c + 1 < NC);

        // phase 1: prefetch next A (latency hides behind ks=0 MMAs)
        if (more) {
            const float* ap = aRow + (c + 1) * 32;
#pragma unroll
            for (int i = 0; i < 4; ++i)
                stage4[i] = reinterpret_cast<const float4*>(ap)[i];
        }

#pragma unroll
        for (int ks = 0; ks < 2; ++ks) {
            uint32_t bh[2][4], bl[2][4];
#pragma unroll
            for (int j = 0; j < 2; ++j) {
                ldsm4(bh[j], swz(bBh, lbRow + j * 16, ks * 2 + lbKg));
                ldsm4(bl[j], swz(bBl, lbRow + j * 16, ks * 2 + lbKg));
            }
#pragma unroll
            for (int mp = 0; mp < 2; ++mp) {
                uint32_t ah[2][4], al[2][4];
#pragma unroll
                for (int q = 0; q < 2; ++q) {
                    int mt = mp * 2 + q;
                    ldsm4(ah[q], swz(bAh, laRow + mt * 16, ks * 2 + laKg));
                    ldsm4(al[q], swz(bAl, laRow + mt * 16, ks * 2 + laKg));
                }
#pragma unroll
                for (int q = 0; q < 2; ++q) {
                    int mt = mp * 2 + q;
#pragma unroll
                    for (int nt = 0; nt < 4; ++nt) {
                        const uint32_t* bph = &bh[nt >> 1][(nt & 1) * 2];
                        const uint32_t* bpl = &bl[nt >> 1][(nt & 1) * 2];
                        mma16816(acc[mt][nt], ah[q], bph);
                        mma16816(acc[mt][nt], ah[q], bpl);
                        mma16816(acc[mt][nt], al[q], bph);
                    }
                }
            }

            // between the two k-steps: flush A(c+1), prefetch B(c+1)
            if (ks == 0 && more) {
                cvt_sts(stage4, nbase, nbase + 8192, r, g0);
                const float* bp = bRow + (c + 1) * 32;
#pragma unroll
                for (int i = 0; i < 4; ++i)
                    stage4[i] = reinterpret_cast<const float4*>(bp)[i];
            }
        }

        if (more) cvt_sts(stage4, nbase + 16384, nbase + 24576, r, g0);
        __syncthreads();
    }

    // epilogue: direct global stores (8B per lane per sub-tile row)
#pragma unroll
    for (int mt = 0; mt < 4; ++mt) {
#pragma unroll
        for (int nt = 0; nt < 4; ++nt) {
            int row = bm + warpM + mt * 16 + (lane >> 2);
            int col = bn + warpN + nt * 8 + (lane & 3) * 2;
            float2 v0 = make_float2(acc[mt][nt][0], acc[mt][nt][1]);
            float2 v1 = make_float2(acc[mt][nt][2], acc[mt][nt][3]);
            *reinterpret_cast<float2*>(C + (size_t)row * N + col) = v0;
            *reinterpret_cast<float2*>(C + (size_t)(row + 8) * N + col) = v1;
        }
    }
}

// ---------------------------------------------------------------------------
// Kernel 0: softmax convolution coefficients (parallel float)
// ---------------------------------------------------------------------------
__global__ void coeff_kernel() {
    __shared__ float warp_sum[12];
    const int j = threadIdx.x;
    const int lane = j & 31, warp = j >> 5;
    const float c = -logf(10000.0f) / 384.0f;
    const float f = __expf(c * (float)j);
    for (int d = 0; d <= DMAX; ++d) {
        float val = cosf((float)d * f);
#pragma unroll
        for (int o = 16; o; o >>= 1) val += __shfl_xor_sync(0xffffffffu, val, o);
        if (lane == 0) warp_sum[warp] = val;
        __syncthreads();
        if (j == 0) {
            float w = 0.f;
#pragma unroll
            for (int i = 0; i < 12; ++i) w += warp_sum[i];
            g_e[d] = expf(w - 384.0f);
        }
        __syncthreads();
    }
}

// ---------------------------------------------------------------------------
// Kernel 2: softmax == normalized 15-tap convolution along seq
// ---------------------------------------------------------------------------
__global__ void smooth_kernel() {
    const int NC4 = KV / 4;
    int idx = blockIdx.x * blockDim.x + threadIdx.x;
    if (idx >= MTOT * NC4) return;
    int m = idx / NC4;
    int c = idx - m * NC4;
    int s = m & (SEQ - 1);

    const float4* vp = reinterpret_cast<const float4*>(g_v);
    float4 acc = vp[(size_t)m * NC4 + c];
    float z = 1.0f;
#pragma unroll
    for (int d = 1; d <= DMAX; ++d) {
        float e = g_e[d];
        if (s >= d) {
            float4 v = vp[(size_t)(m - d) * NC4 + c];
            acc.x += e * v.x; acc.y += e * v.y;
            acc.z += e * v.z; acc.w += e * v.w;
            z += e;
        }
        if (s + d < SEQ) {
            float4 v = vp[(size_t)(m + d) * NC4 + c];
            acc.x += e * v.x; acc.y += e * v.y;
            acc.z += e * v.z; acc.w += e * v.w;
            z += e;
        }
    }
    float inv = 1.0f / z;
    float4 o;
    o.x = acc.x * inv; o.y = acc.y * inv;
    o.z = acc.z * inv; o.w = acc.w * inv;
    reinterpret_cast<float4*>(g_a)[(size_t)m * NC4 + c] = o;
}

// ---------------------------------------------------------------------------
// Launch
// ---------------------------------------------------------------------------
extern "C" void kernel_launch(void* const* d_in, const int* in_sizes, int n_in,
                              void* d_out, int out_size) {
    const float* x  = (const float*)d_in[0];
    // d_in[1] = Wq, d_in[2] = Wk are dead (rope ignores its input)
    const float* Wv = (const float*)d_in[3];
    const float* Wo = (const float*)d_in[4];
    float* out = (float*)d_out;

    float* v_buf;  cudaGetSymbolAddress((void**)&v_buf, g_v);
    float* a_buf;  cudaGetSymbolAddress((void**)&a_buf, g_a);

    const int SMEM_BYTES = 65536 + 128;
    cudaFuncSetAttribute(gemm_mma, cudaFuncAttributeMaxDynamicSharedMemorySize,
                         SMEM_BYTES);

    coeff_kernel<<<1, 384>>>();

    // 1) v = x @ Wv^T : [16384,768] x [256,768]
    gemm_mma<<<dim3(KV / 128, MTOT / 128), 256, SMEM_BYTES>>>(
        x, Wv, v_buf, MTOT, KV, HIDDEN);

    // 2) softmax(attn) @ v == normalized 15-tap convolution
    {
        int n = MTOT * (KV / 4);
        smooth_kernel<<<(n + 255) / 256, 256>>>();
    }

    // 3) out = a @ Wo^T : [16384,256] x [768,256]
    gemm_mma<<<dim3(HIDDEN / 128, MTOT / 128), 256, SMEM_BYTES>>>(
        a_buf, Wo, out, MTOT, HIDDEN, KV);
}

// round 6
// speedup vs baseline: 5.0448x; 1.1333x over previous
#include <cuda_runtime.h>
#include <math.h>
#include <stdint.h>

// Problem constants
#define SEQ     8192
#define BATCH   2
#define MTOT    (BATCH * SEQ)   // 16384
#define HIDDEN  768
#define KV      256
#define DMAX    7

// Scratch (static __device__ — no runtime allocation allowed)
__device__ float g_e[DMAX + 1];
__device__ __align__(16) float g_v[MTOT * KV];
__device__ __align__(16) float g_a[MTOT * KV];

// ---------------------------------------------------------------------------
// helpers
// ---------------------------------------------------------------------------
__device__ __forceinline__ uint32_t smem_u32(const void* p) {
    uint32_t a;
    asm("{ .reg .u64 t; cvta.to.shared.u64 t, %1; cvt.u32.u64 %0, t; }"
        : "=r"(a) : "l"(p));
    return a;
}

__device__ __forceinline__ uint32_t to_tf32(float x) {
    uint32_t u;
    asm("cvt.rna.tf32.f32 %0, %1;" : "=r"(u) : "f"(x));
    return u;
}

__device__ __forceinline__ void mma_tf32(float* d, const uint32_t* a,
                                         const uint32_t* b) {
    asm volatile(
        "mma.sync.aligned.m16n8k8.row.col.f32.tf32.tf32.f32 "
        "{%0,%1,%2,%3}, {%4,%5,%6,%7}, {%8,%9}, {%0,%1,%2,%3};"
        : "+f"(d[0]), "+f"(d[1]), "+f"(d[2]), "+f"(d[3])
        : "r"(a[0]), "r"(a[1]), "r"(a[2]), "r"(a[3]), "r"(b[0]), "r"(b[1]));
}

#define CP_ASYNC16(dst, src) \
    asm volatile("cp.async.cg.shared.global [%0], [%1], 16;" \
                 :: "r"(dst), "l"(src) : "memory")
#define CP_COMMIT() asm volatile("cp.async.commit_group;" ::: "memory")
#define CP_WAIT1()  asm volatile("cp.async.wait_group 1;" ::: "memory")
#define CP_WAIT0()  asm volatile("cp.async.wait_group 0;" ::: "memory")

// SMEM geometry: rows padded to 36 floats (144B) -> conflict-free frag LDS
#define ROWF   36
#define ATILE  (128 * ROWF * 4)            // 18432 B
#define STGB   (2 * ATILE)                 // A + B per stage = 36864 B
#define NSTAGE 3

// ---------------------------------------------------------------------------
// Single-pass TF32 tensor-core GEMM (NT): C[m,n] = sum_k A[m*K+k]*B[n*K+k]
// fp32 in/out, tf32 mma (cvt.rna on fragments -> unbiased, rel err ~4e-4).
// 128x128 CTA tile, BK=32, 8 warps (2x4), warp tile 64x32, m16n8k8.
// 3-stage cp.async pipeline, one __syncthreads per chunk.
// M, N multiples of 128; K multiple of 32.
// ---------------------------------------------------------------------------
__global__ __launch_bounds__(256, 2) void gemm_tf32(
    const float* __restrict__ A, const float* __restrict__ B,
    float* __restrict__ C, int M, int N, int K)
{
    extern __shared__ char dynsmem[];
    const uint32_t sb = (smem_u32(dynsmem) + 127u) & ~127u;

    const int tid  = threadIdx.x;
    const int wid  = tid >> 5;
    const int lane = tid & 31;
    const int bm   = blockIdx.y * 128;
    const int bn   = blockIdx.x * 128;
    const int NC   = K >> 5;

    const int warpM = (wid >> 2) * 64;   // 0 or 64
    const int warpN = (wid & 3) * 32;    // 0..96

    // cp.async mapping: thread -> (row 0..127, 16-float half of the 32 chunk)
    const int r = tid >> 1;
    const int h = tid & 1;
    const float* gA = A + (size_t)(bm + r) * K + h * 16;
    const float* gB = B + (size_t)(bn + r) * K + h * 16;
    const uint32_t sOffB = (uint32_t)(r * ROWF + h * 16) * 4u;

    float acc[4][4][4];
#pragma unroll
    for (int i = 0; i < 4; ++i)
#pragma unroll
        for (int j = 0; j < 4; ++j)
#pragma unroll
            for (int q = 0; q < 4; ++q) acc[i][j][q] = 0.f;

#define ISSUE_STAGE(stg, kt)                                              \
    do {                                                                  \
        uint32_t dA = sb + (uint32_t)(stg) * STGB + sOffB;                \
        uint32_t dB = dA + ATILE;                                         \
        const float* pa = gA + (kt);                                      \
        const float* pb = gB + (kt);                                      \
        CP_ASYNC16(dA,      pa);                                          \
        CP_ASYNC16(dA + 16, pa + 4);                                      \
        CP_ASYNC16(dA + 32, pa + 8);                                      \
        CP_ASYNC16(dA + 48, pa + 12);                                     \
        CP_ASYNC16(dB,      pb);                                          \
        CP_ASYNC16(dB + 16, pb + 4);                                      \
        CP_ASYNC16(dB + 32, pb + 8);                                      \
        CP_ASYNC16(dB + 48, pb + 12);                                     \
        CP_COMMIT();                                                      \
    } while (0)

    // prologue: stages 0 and 1 in flight
    ISSUE_STAGE(0, 0);
    ISSUE_STAGE(1, 32);

    // fragment lane addressing (floats)
    const int aR = warpM + (lane >> 2);       // A row base
    const int aC = lane & 3;                  // A col base
    const int bR = warpN + (lane >> 2);       // B row (n) base
    const int bC = lane & 3;                  // B col (k) base

    int stage = 0;
    for (int c = 0; c < NC; ++c) {
        CP_WAIT1();
        __syncthreads();

        // refill pipeline (write stage == (c+2)%3, consumed two iters ahead)
        if (c + 2 < NC) {
            int ns = stage + 2; if (ns >= NSTAGE) ns -= NSTAGE;
            ISSUE_STAGE(ns, (c + 2) * 32);
        }

        const uint32_t sA = sb + (uint32_t)stage * STGB;
        const uint32_t sB = sA + ATILE;

#pragma unroll
        for (int ks = 0; ks < 4; ++ks) {
            const int kc = ks * 8;
            // B fragments: 4 n-tiles x 2 regs
            uint32_t bf[4][2];
#pragma unroll
            for (int nt = 0; nt < 4; ++nt) {
                uint32_t ad = sB + (uint32_t)((bR + nt * 8) * ROWF + kc + bC) * 4u;
                float f0, f1;
                asm volatile("ld.shared.f32 %0, [%1];" : "=f"(f0) : "r"(ad));
                asm volatile("ld.shared.f32 %0, [%1];" : "=f"(f1) : "r"(ad + 16));
                bf[nt][0] = to_tf32(f0);
                bf[nt][1] = to_tf32(f1);
            }
            // A fragments: 4 m-tiles x 4 regs, then MMAs
#pragma unroll
            for (int mt = 0; mt < 4; ++mt) {
                uint32_t ad = sA + (uint32_t)((aR + mt * 16) * ROWF + kc + aC) * 4u;
                float f0, f1, f2, f3;
                asm volatile("ld.shared.f32 %0, [%1];" : "=f"(f0) : "r"(ad));
                asm volatile("ld.shared.f32 %0, [%1];" : "=f"(f1) : "r"(ad + 8 * ROWF * 4));
                asm volatile("ld.shared.f32 %0, [%1];" : "=f"(f2) : "r"(ad + 16));
                asm volatile("ld.shared.f32 %0, [%1];" : "=f"(f3) : "r"(ad + 8 * ROWF * 4 + 16));
                uint32_t af[4];
                af[0] = to_tf32(f0); af[1] = to_tf32(f1);
                af[2] = to_tf32(f2); af[3] = to_tf32(f3);
#pragma unroll
                for (int nt = 0; nt < 4; ++nt)
                    mma_tf32(acc[mt][nt], af, bf[nt]);
            }
        }

        __syncthreads();
        if (++stage >= NSTAGE) stage = 0;
    }
    CP_WAIT0();

    // epilogue: direct global stores (8B per lane per sub-tile row)
#pragma unroll
    for (int mt = 0; mt < 4; ++mt) {
#pragma unroll
        for (int nt = 0; nt < 4; ++nt) {
            int row = bm + warpM + mt * 16 + (lane >> 2);
            int col = bn + warpN + nt * 8 + (lane & 3) * 2;
            float2 v0 = make_float2(acc[mt][nt][0], acc[mt][nt][1]);
            float2 v1 = make_float2(acc[mt][nt][2], acc[mt][nt][3]);
            *reinterpret_cast<float2*>(C + (size_t)row * N + col) = v0;
            *reinterpret_cast<float2*>(C + (size_t)(row + 8) * N + col) = v1;
        }
    }
#undef ISSUE_STAGE
}

// ---------------------------------------------------------------------------
// Kernel 0: softmax convolution coefficients (parallel float)
// ---------------------------------------------------------------------------
__global__ void coeff_kernel() {
    __shared__ float warp_sum[12];
    const int j = threadIdx.x;
    const int lane = j & 31, warp = j >> 5;
    const float c = -logf(10000.0f) / 384.0f;
    const float f = __expf(c * (float)j);
    for (int d = 0; d <= DMAX; ++d) {
        float val = cosf((float)d * f);
#pragma unroll
        for (int o = 16; o; o >>= 1) val += __shfl_xor_sync(0xffffffffu, val, o);
        if (lane == 0) warp_sum[warp] = val;
        __syncthreads();
        if (j == 0) {
            float w = 0.f;
#pragma unroll
            for (int i = 0; i < 12; ++i) w += warp_sum[i];
            g_e[d] = expf(w - 384.0f);
        }
        __syncthreads();
    }
}

// ---------------------------------------------------------------------------
// Kernel 2: softmax == normalized 15-tap convolution along seq
// ---------------------------------------------------------------------------
__global__ void smooth_kernel() {
    const int NC4 = KV / 4;
    int idx = blockIdx.x * blockDim.x + threadIdx.x;
    if (idx >= MTOT * NC4) return;
    int m = idx / NC4;
    int c = idx - m * NC4;
    int s = m & (SEQ - 1);

    const float4* vp = reinterpret_cast<const float4*>(g_v);
    float4 acc = vp[(size_t)m * NC4 + c];
    float z = 1.0f;
#pragma unroll
    for (int d = 1; d <= DMAX; ++d) {
        float e = g_e[d];
        if (s >= d) {
            float4 v = vp[(size_t)(m - d) * NC4 + c];
            acc.x += e * v.x; acc.y += e * v.y;
            acc.z += e * v.z; acc.w += e * v.w;
            z += e;
        }
        if (s + d < SEQ) {
            float4 v = vp[(size_t)(m + d) * NC4 + c];
            acc.x += e * v.x; acc.y += e * v.y;
            acc.z += e * v.z; acc.w += e * v.w;
            z += e;
        }
    }
    float inv = 1.0f / z;
    float4 o;
    o.x = acc.x * inv; o.y = acc.y * inv;
    o.z = acc.z * inv; o.w = acc.w * inv;
    reinterpret_cast<float4*>(g_a)[(size_t)m * NC4 + c] = o;
}

// ---------------------------------------------------------------------------
// Launch
// ---------------------------------------------------------------------------
extern "C" void kernel_launch(void* const* d_in, const int* in_sizes, int n_in,
                              void* d_out, int out_size) {
    const float* x  = (const float*)d_in[0];
    // d_in[1] = Wq, d_in[2] = Wk are dead (rope ignores its input)
    const float* Wv = (const float*)d_in[3];
    const float* Wo = (const float*)d_in[4];
    float* out = (float*)d_out;

    float* v_buf;  cudaGetSymbolAddress((void**)&v_buf, g_v);
    float* a_buf;  cudaGetSymbolAddress((void**)&a_buf, g_a);

    const int SMEM_BYTES = NSTAGE * STGB + 128;   // ~108 KB
    cudaFuncSetAttribute(gemm_tf32, cudaFuncAttributeMaxDynamicSharedMemorySize,
                         SMEM_BYTES);

    coeff_kernel<<<1, 384>>>();

    // 1) v = x @ Wv^T : [16384,768] x [256,768]
    gemm_tf32<<<dim3(KV / 128, MTOT / 128), 256, SMEM_BYTES>>>(
        x, Wv, v_buf, MTOT, KV, HIDDEN);

    // 2) softmax(attn) @ v == normalized 15-tap convolution
    {
        int n = MTOT * (KV / 4);
        smooth_kernel<<<(n + 255) / 256, 256>>>();
    }

    // 3) out = a @ Wo^T : [16384,256] x [768,256]
    gemm_tf32<<<dim3(HIDDEN / 128, MTOT / 128), 256, SMEM_BYTES>>>(
        a_buf, Wo, out, MTOT, HIDDEN, KV);
}

// round 7
// speedup vs baseline: 5.2167x; 1.0341x over previous
#include <cuda_runtime.h>
#include <math.h>
#include <stdint.h>

// Problem constants
#define SEQ     8192
#define BATCH   2
#define MTOT    (BATCH * SEQ)   // 16384
#define HIDDEN  768
#define KV      256
#define DMAX    7

// Scratch (static __device__ — no runtime allocation allowed)
__device__ float g_e[DMAX + 1];
__device__ __align__(16) float g_v[MTOT * KV];
__device__ __align__(16) float g_a[MTOT * KV];

// ---------------------------------------------------------------------------
// helpers
// ---------------------------------------------------------------------------
__device__ __forceinline__ uint32_t smem_u32(const void* p) {
    uint32_t a;
    asm("{ .reg .u64 t; cvta.to.shared.u64 t, %1; cvt.u32.u64 %0, t; }"
        : "=r"(a) : "l"(p));
    return a;
}

__device__ __forceinline__ uint32_t to_tf32_u(uint32_t x) {
    uint32_t u;
    asm("cvt.rna.tf32.f32 %0, %1;" : "=r"(u) : "f"(__uint_as_float(x)));
    return u;
}

__device__ __forceinline__ void ldsm4(uint32_t* r, uint32_t addr) {
    asm volatile("ldmatrix.sync.aligned.m8n8.x4.shared.b16 {%0,%1,%2,%3}, [%4];"
        : "=r"(r[0]), "=r"(r[1]), "=r"(r[2]), "=r"(r[3]) : "r"(addr));
}

__device__ __forceinline__ void mma_tf32(float* d, const uint32_t* a,
                                         const uint32_t* b) {
    asm volatile(
        "mma.sync.aligned.m16n8k8.row.col.f32.tf32.tf32.f32 "
        "{%0,%1,%2,%3}, {%4,%5,%6,%7}, {%8,%9}, {%0,%1,%2,%3};"
        : "+f"(d[0]), "+f"(d[1]), "+f"(d[2]), "+f"(d[3])
        : "r"(a[0]), "r"(a[1]), "r"(a[2]), "r"(a[3]), "r"(b[0]), "r"(b[1]));
}

#define CP_ASYNC16(dst, src) \
    asm volatile("cp.async.cg.shared.global [%0], [%1], 16;" \
                 :: "r"(dst), "l"(src) : "memory")
#define CP_COMMIT() asm volatile("cp.async.commit_group;" ::: "memory")
#define CP_WAIT1()  asm volatile("cp.async.wait_group 1;" ::: "memory")
#define CP_WAIT0()  asm volatile("cp.async.wait_group 0;" ::: "memory")

// SMEM geometry: rows padded to 36 floats (144B).
// ldmatrix row addresses: 8 rows at 144B stride land on distinct 16B chunks
// mod 128B -> conflict-free.
#define ROWF   36
#define ATILE  (128 * ROWF * 4)            // 18432 B
#define STGB   (2 * ATILE)                 // A + B per stage = 36864 B
#define NSTAGE 3

// ---------------------------------------------------------------------------
// Single-pass TF32 tensor-core GEMM (NT): C[m,n] = sum_k A[m*K+k]*B[n*K+k]
// fp32 in/out, tf32 mma (cvt.rna on fragments -> unbiased, rel err ~4e-4).
// 128x128 CTA tile, BK=32, 8 warps (2x4), warp tile 64x32, m16n8k8.
// Fragments loaded via ldmatrix.x4 (tf32-as-2xb16 trick): one instruction
// yields a full 4-reg A fragment / two 2-reg B fragments.
// 3-stage cp.async pipeline, one __syncthreads per chunk.
// M, N multiples of 128; K multiple of 32.
// ---------------------------------------------------------------------------
__global__ __launch_bounds__(256, 2) void gemm_tf32(
    const float* __restrict__ A, const float* __restrict__ B,
    float* __restrict__ C, int M, int N, int K)
{
    extern __shared__ char dynsmem[];
    const uint32_t sb = (smem_u32(dynsmem) + 127u) & ~127u;

    const int tid  = threadIdx.x;
    const int wid  = tid >> 5;
    const int lane = tid & 31;
    const int bm   = blockIdx.y * 128;
    const int bn   = blockIdx.x * 128;
    const int NC   = K >> 5;

    const int warpM = (wid >> 2) * 64;   // 0 or 64
    const int warpN = (wid & 3) * 32;    // 0..96

    // cp.async mapping: thread -> (row 0..127, 16-float half of the 32 chunk)
    const int r = tid >> 1;
    const int h = tid & 1;
    const float* gA = A + (size_t)(bm + r) * K + h * 16;
    const float* gB = B + (size_t)(bn + r) * K + h * 16;
    const uint32_t sOffB = (uint32_t)(r * ROWF + h * 16) * 4u;

    float acc[4][4][4];
#pragma unroll
    for (int i = 0; i < 4; ++i)
#pragma unroll
        for (int j = 0; j < 4; ++j)
#pragma unroll
            for (int q = 0; q < 4; ++q) acc[i][j][q] = 0.f;

#define ISSUE_STAGE(stg, kt)                                              \
    do {                                                                  \
        uint32_t dA = sb + (uint32_t)(stg) * STGB + sOffB;                \
        uint32_t dB = dA + ATILE;                                         \
        const float* pa = gA + (kt);                                      \
        const float* pb = gB + (kt);                                      \
        CP_ASYNC16(dA,      pa);                                          \
        CP_ASYNC16(dA + 16, pa + 4);                                      \
        CP_ASYNC16(dA + 32, pa + 8);                                      \
        CP_ASYNC16(dA + 48, pa + 12);                                     \
        CP_ASYNC16(dB,      pb);                                          \
        CP_ASYNC16(dB + 16, pb + 4);                                      \
        CP_ASYNC16(dB + 32, pb + 8);                                      \
        CP_ASYNC16(dB + 48, pb + 12);                                     \
        CP_COMMIT();                                                      \
    } while (0)

    // prologue: stages 0 and 1 in flight
    ISSUE_STAGE(0, 0);
    ISSUE_STAGE(1, 32);

    // ldmatrix lane->address components (float offsets; x4 matrix = lane>>3)
    // A: matrices {(r,c),(r+8,c),(r,c+4),(r+8,c+4)} -> regs a0..a3
    const uint32_t aOffF = (uint32_t)((warpM + (lane & 7) + 8 * ((lane >> 3) & 1))
                                      * ROWF + 4 * (lane >> 4));
    // B: matrices {nt0:(n,kc),(n,kc+4), nt1:(n+8,kc),(n+8,kc+4)} -> b0/b1 pairs
    const uint32_t bOffF = (uint32_t)((warpN + ((lane >> 4) << 3) + (lane & 7))
                                      * ROWF + 4 * ((lane >> 3) & 1));

    int stage = 0;
    for (int c = 0; c < NC; ++c) {
        CP_WAIT1();
        __syncthreads();

        // refill pipeline (write stage == (c+2)%3, consumed two iters ahead)
        if (c + 2 < NC) {
            int ns = stage + 2; if (ns >= NSTAGE) ns -= NSTAGE;
            ISSUE_STAGE(ns, (c + 2) * 32);
        }

        const uint32_t sA = sb + (uint32_t)stage * STGB + aOffF * 4u;
        const uint32_t sB = sb + (uint32_t)stage * STGB + ATILE + bOffF * 4u;

#pragma unroll
        for (int ks = 0; ks < 4; ++ks) {
            const uint32_t kb = (uint32_t)(ks * 8) * 4u;
            // B fragments: 2 ldmatrix.x4 -> 4 n-tiles x {b0,b1}
            uint32_t bfr[2][4];
            ldsm4(bfr[0], sB + kb);
            ldsm4(bfr[1], sB + kb + 16u * ROWF * 4u);
#pragma unroll
            for (int p = 0; p < 2; ++p)
#pragma unroll
                for (int q = 0; q < 4; ++q) bfr[p][q] = to_tf32_u(bfr[p][q]);

            // A fragments: 1 ldmatrix.x4 per m-tile
            uint32_t af[4][4];
#pragma unroll
            for (int mt = 0; mt < 4; ++mt)
                ldsm4(af[mt], sA + kb + (uint32_t)(mt * 16 * ROWF) * 4u);
#pragma unroll
            for (int mt = 0; mt < 4; ++mt) {
#pragma unroll
                for (int q = 0; q < 4; ++q) af[mt][q] = to_tf32_u(af[mt][q]);
#pragma unroll
                for (int nt = 0; nt < 4; ++nt)
                    mma_tf32(acc[mt][nt], af[mt], &bfr[nt >> 1][(nt & 1) * 2]);
            }
        }

        __syncthreads();
        if (++stage >= NSTAGE) stage = 0;
    }
    CP_WAIT0();

    // epilogue: direct global stores (8B per lane per sub-tile row)
#pragma unroll
    for (int mt = 0; mt < 4; ++mt) {
#pragma unroll
        for (int nt = 0; nt < 4; ++nt) {
            int row = bm + warpM + mt * 16 + (lane >> 2);
            int col = bn + warpN + nt * 8 + (lane & 3) * 2;
            float2 v0 = make_float2(acc[mt][nt][0], acc[mt][nt][1]);
            float2 v1 = make_float2(acc[mt][nt][2], acc[mt][nt][3]);
            *reinterpret_cast<float2*>(C + (size_t)row * N + col) = v0;
            *reinterpret_cast<float2*>(C + (size_t)(row + 8) * N + col) = v1;
        }
    }
#undef ISSUE_STAGE
}

// ---------------------------------------------------------------------------
// Kernel 0: softmax convolution coefficients (parallel float)
// ---------------------------------------------------------------------------
__global__ void coeff_kernel() {
    __shared__ float warp_sum[12];
    const int j = threadIdx.x;
    const int lane = j & 31, warp = j >> 5;
    const float c = -logf(10000.0f) / 384.0f;
    const float f = __expf(c * (float)j);
    for (int d = 0; d <= DMAX; ++d) {
        float val = cosf((float)d * f);
#pragma unroll
        for (int o = 16; o; o >>= 1) val += __shfl_xor_sync(0xffffffffu, val, o);
        if (lane == 0) warp_sum[warp] = val;
        __syncthreads();
        if (j == 0) {
            float w = 0.f;
#pragma unroll
            for (int i = 0; i < 12; ++i) w += warp_sum[i];
            g_e[d] = expf(w - 384.0f);
        }
        __syncthreads();
    }
}

// ---------------------------------------------------------------------------
// Kernel 2: softmax == normalized 15-tap convolution along seq
// ---------------------------------------------------------------------------
__global__ void smooth_kernel() {
    const int NC4 = KV / 4;
    int idx = blockIdx.x * blockDim.x + threadIdx.x;
    if (idx >= MTOT * NC4) return;
    int m = idx / NC4;
    int c = idx - m * NC4;
    int s = m & (SEQ - 1);

    const float4* vp = reinterpret_cast<const float4*>(g_v);
    float4 acc = vp[(size_t)m * NC4 + c];
    float z = 1.0f;
#pragma unroll
    for (int d = 1; d <= DMAX; ++d) {
        float e = g_e[d];
        if (s >= d) {
            float4 v = vp[(size_t)(m - d) * NC4 + c];
            acc.x += e * v.x; acc.y += e * v.y;
            acc.z += e * v.z; acc.w += e * v.w;
            z += e;
        }
        if (s + d < SEQ) {
            float4 v = vp[(size_t)(m + d) * NC4 + c];
            acc.x += e * v.x; acc.y += e * v.y;
            acc.z += e * v.z; acc.w += e * v.w;
            z += e;
        }
    }
    float inv = 1.0f / z;
    float4 o;
    o.x = acc.x * inv; o.y = acc.y * inv;
    o.z = acc.z * inv; o.w = acc.w * inv;
    reinterpret_cast<float4*>(g_a)[(size_t)m * NC4 + c] = o;
}

// ---------------------------------------------------------------------------
// Launch
// ---------------------------------------------------------------------------
extern "C" void kernel_launch(void* const* d_in, const int* in_sizes, int n_in,
                              void* d_out, int out_size) {
    const float* x  = (const float*)d_in[0];
    // d_in[1] = Wq, d_in[2] = Wk are dead (rope ignores its input)
    const float* Wv = (const float*)d_in[3];
    const float* Wo = (const float*)d_in[4];
    float* out = (float*)d_out;

    float* v_buf;  cudaGetSymbolAddress((void**)&v_buf, g_v);
    float* a_buf;  cudaGetSymbolAddress((void**)&a_buf, g_a);

    const int SMEM_BYTES = NSTAGE * STGB + 128;   // ~108 KB
    cudaFuncSetAttribute(gemm_tf32, cudaFuncAttributeMaxDynamicSharedMemorySize,
                         SMEM_BYTES);

    coeff_kernel<<<1, 384>>>();

    // 1) v = x @ Wv^T : [16384,768] x [256,768]
    gemm_tf32<<<dim3(KV / 128, MTOT / 128), 256, SMEM_BYTES>>>(
        x, Wv, v_buf, MTOT, KV, HIDDEN);

    // 2) softmax(attn) @ v == normalized 15-tap convolution
    {
        int n = MTOT * (KV / 4);
        smooth_kernel<<<(n + 255) / 256, 256>>>();
    }

    // 3) out = a @ Wo^T : [16384,256] x [768,256]
    gemm_tf32<<<dim3(HIDDEN / 128, MTOT / 128), 256, SMEM_BYTES>>>(
        a_buf, Wo, out, MTOT, HIDDEN, KV);
}

// round 8
// speedup vs baseline: 5.4369x; 1.0422x over previous
#include <cuda_runtime.h>
#include <math.h>
#include <stdint.h>

// Problem constants
#define SEQ     8192
#define BATCH   2
#define MTOT    (BATCH * SEQ)   // 16384
#define HIDDEN  768
#define KV      256
#define DMAX    7

// Scratch (static __device__ — no runtime allocation allowed)
__device__ float g_e[DMAX + 1];
__device__ __align__(16) float g_v[MTOT * KV];
__device__ __align__(16) float g_a[MTOT * KV];
__device__ __align__(16) float g_wv[KV * HIDDEN];   // tf32-pre-rounded Wv
__device__ __align__(16) float g_wo[HIDDEN * KV];   // tf32-pre-rounded Wo

// ---------------------------------------------------------------------------
// helpers
// ---------------------------------------------------------------------------
__device__ __forceinline__ uint32_t smem_u32(const void* p) {
    uint32_t a;
    asm("{ .reg .u64 t; cvta.to.shared.u64 t, %1; cvt.u32.u64 %0, t; }"
        : "=r"(a) : "l"(p));
    return a;
}

__device__ __forceinline__ uint32_t to_tf32_u(uint32_t x) {
    uint32_t u;
    asm("cvt.rna.tf32.f32 %0, %1;" : "=r"(u) : "f"(__uint_as_float(x)));
    return u;
}
__device__ __forceinline__ float to_tf32_f(float x) {
    uint32_t u;
    asm("cvt.rna.tf32.f32 %0, %1;" : "=r"(u) : "f"(x));
    return __uint_as_float(u);
}

__device__ __forceinline__ void ldsm4(uint32_t* r, uint32_t addr) {
    asm volatile("ldmatrix.sync.aligned.m8n8.x4.shared.b16 {%0,%1,%2,%3}, [%4];"
        : "=r"(r[0]), "=r"(r[1]), "=r"(r[2]), "=r"(r[3]) : "r"(addr));
}

__device__ __forceinline__ void mma_tf32(float* d, const uint32_t* a,
                                         const uint32_t* b) {
    asm volatile(
        "mma.sync.aligned.m16n8k8.row.col.f32.tf32.tf32.f32 "
        "{%0,%1,%2,%3}, {%4,%5,%6,%7}, {%8,%9}, {%0,%1,%2,%3};"
        : "+f"(d[0]), "+f"(d[1]), "+f"(d[2]), "+f"(d[3])
        : "r"(a[0]), "r"(a[1]), "r"(a[2]), "r"(a[3]), "r"(b[0]), "r"(b[1]));
}

#define CP_ASYNC16(dst, src) \
    asm volatile("cp.async.cg.shared.global [%0], [%1], 16;" \
                 :: "r"(dst), "l"(src) : "memory")
#define CP_COMMIT() asm volatile("cp.async.commit_group;" ::: "memory")
#define CP_WAIT1()  asm volatile("cp.async.wait_group 1;" ::: "memory")
#define CP_WAIT0()  asm volatile("cp.async.wait_group 0;" ::: "memory")

// SMEM geometry: rows padded to 36 floats (144B) -> conflict-free ldmatrix
#define ROWF   36
#define ATILE  (128 * ROWF * 4)            // 18432 B
#define STGB   (2 * ATILE)                 // A + B per stage = 36864 B
#define NSTAGE 3

// ---------------------------------------------------------------------------
// Single-pass TF32 tensor-core GEMM (NT): C[m,n] = sum_k A[m*K+k]*B[n*K+k]
// fp32 in/out, tf32 mma. CVT_A/CVT_B select whether fragments still need
// tf32 rounding (skipped when the source array is pre-rounded -> cvt.rna is
// idempotent, results bit-identical).
// 128x128 CTA tile, BK=32, 8 warps (2x4), warp tile 64x32, m16n8k8.
// 3-stage cp.async pipeline, ONE __syncthreads per chunk, B-fragment
// prefetch across ks steps.
// ---------------------------------------------------------------------------
template <bool CVT_A, bool CVT_B>
__global__ __launch_bounds__(256, 2) void gemm_tf32(
    const float* __restrict__ A, const float* __restrict__ B,
    float* __restrict__ C, int M, int N, int K)
{
    extern __shared__ char dynsmem[];
    const uint32_t sb = (smem_u32(dynsmem) + 127u) & ~127u;

    const int tid  = threadIdx.x;
    const int wid  = tid >> 5;
    const int lane = tid & 31;
    const int bm   = blockIdx.y * 128;
    const int bn   = blockIdx.x * 128;
    const int NC   = K >> 5;

    const int warpM = (wid >> 2) * 64;   // 0 or 64
    const int warpN = (wid & 3) * 32;    // 0..96

    // cp.async mapping: thread -> (row 0..127, 16-float half of the 32 chunk)
    const int r = tid >> 1;
    const int h = tid & 1;
    const float* gA = A + (size_t)(bm + r) * K + h * 16;
    const float* gB = B + (size_t)(bn + r) * K + h * 16;
    const uint32_t sOffB = (uint32_t)(r * ROWF + h * 16) * 4u;

    float acc[4][4][4];
#pragma unroll
    for (int i = 0; i < 4; ++i)
#pragma unroll
        for (int j = 0; j < 4; ++j)
#pragma unroll
            for (int q = 0; q < 4; ++q) acc[i][j][q] = 0.f;

#define ISSUE_STAGE(stg, kt)                                              \
    do {                                                                  \
        uint32_t dA = sb + (uint32_t)(stg) * STGB + sOffB;                \
        uint32_t dB = dA + ATILE;                                         \
        const float* pa = gA + (kt);                                      \
        const float* pb = gB + (kt);                                      \
        CP_ASYNC16(dA,      pa);                                          \
        CP_ASYNC16(dA + 16, pa + 4);                                      \
        CP_ASYNC16(dA + 32, pa + 8);                                      \
        CP_ASYNC16(dA + 48, pa + 12);                                     \
        CP_ASYNC16(dB,      pb);                                          \
        CP_ASYNC16(dB + 16, pb + 4);                                      \
        CP_ASYNC16(dB + 32, pb + 8);                                      \
        CP_ASYNC16(dB + 48, pb + 12);                                     \
        CP_COMMIT();                                                      \
    } while (0)

    // prologue: stages 0 and 1 in flight
    ISSUE_STAGE(0, 0);
    ISSUE_STAGE(1, 32);

    // ldmatrix lane->address components (float offsets; x4 matrix = lane>>3)
    const uint32_t aOffF = (uint32_t)((warpM + (lane & 7) + 8 * ((lane >> 3) & 1))
                                      * ROWF + 4 * (lane >> 4));
    const uint32_t bOffF = (uint32_t)((warpN + ((lane >> 4) << 3) + (lane & 7))
                                      * ROWF + 4 * ((lane >> 3) & 1));

    int stage = 0;
    for (int c = 0; c < NC; ++c) {
        CP_WAIT1();
        __syncthreads();   // single barrier: data ready + prev chunk reads done

        // refill pipeline (safe: overwritten stage was read in chunk c-1,
        // whose reads finished before the barrier above)
        if (c + 2 < NC) {
            int ns = stage + 2; if (ns >= NSTAGE) ns -= NSTAGE;
            ISSUE_STAGE(ns, (c + 2) * 32);
        }

        const uint32_t sA = sb + (uint32_t)stage * STGB + aOffF * 4u;
        const uint32_t sB = sb + (uint32_t)stage * STGB + ATILE + bOffF * 4u;

        // B fragments for ks=0
        uint32_t bfr[2][2][4];   // [buf][half][4]
        ldsm4(bfr[0][0], sB);
        ldsm4(bfr[0][1], sB + 16u * ROWF * 4u);

#pragma unroll
        for (int ks = 0; ks < 4; ++ks) {
            const int cur = ks & 1;
            const uint32_t kb = (uint32_t)(ks * 8) * 4u;

            // A fragments for this ks
            uint32_t af[4][4];
#pragma unroll
            for (int mt = 0; mt < 4; ++mt)
                ldsm4(af[mt], sA + kb + (uint32_t)(mt * 16 * ROWF) * 4u);

            // prefetch B fragments for next ks (overlaps MMAs below)
            if (ks < 3) {
                const uint32_t kn = (uint32_t)((ks + 1) * 8) * 4u;
                ldsm4(bfr[cur ^ 1][0], sB + kn);
                ldsm4(bfr[cur ^ 1][1], sB + kn + 16u * ROWF * 4u);
            }

            if (CVT_B) {
#pragma unroll
                for (int p = 0; p < 2; ++p)
#pragma unroll
                    for (int q = 0; q < 4; ++q)
                        bfr[cur][p][q] = to_tf32_u(bfr[cur][p][q]);
            }
#pragma unroll
            for (int mt = 0; mt < 4; ++mt) {
                if (CVT_A) {
#pragma unroll
                    for (int q = 0; q < 4; ++q)
                        af[mt][q] = to_tf32_u(af[mt][q]);
                }
#pragma unroll
                for (int nt = 0; nt < 4; ++nt)
                    mma_tf32(acc[mt][nt], af[mt],
                             &bfr[cur][nt >> 1][(nt & 1) * 2]);
            }
        }

        if (++stage >= NSTAGE) stage = 0;
    }
    CP_WAIT0();

    // epilogue: direct global stores (8B per lane per sub-tile row)
#pragma unroll
    for (int mt = 0; mt < 4; ++mt) {
#pragma unroll
        for (int nt = 0; nt < 4; ++nt) {
            int row = bm + warpM + mt * 16 + (lane >> 2);
            int col = bn + warpN + nt * 8 + (lane & 3) * 2;
            float2 v0 = make_float2(acc[mt][nt][0], acc[mt][nt][1]);
            float2 v1 = make_float2(acc[mt][nt][2], acc[mt][nt][3]);
            *reinterpret_cast<float2*>(C + (size_t)row * N + col) = v0;
            *reinterpret_cast<float2*>(C + (size_t)(row + 8) * N + col) = v1;
        }
    }
#undef ISSUE_STAGE
}

// ---------------------------------------------------------------------------
// Kernel 0: softmax convolution coefficients (parallel float)
// ---------------------------------------------------------------------------
__global__ void coeff_kernel() {
    __shared__ float warp_sum[12];
    const int j = threadIdx.x;
    const int lane = j & 31, warp = j >> 5;
    const float c = -logf(10000.0f) / 384.0f;
    const float f = __expf(c * (float)j);
    for (int d = 0; d <= DMAX; ++d) {
        float val = cosf((float)d * f);
#pragma unroll
        for (int o = 16; o; o >>= 1) val += __shfl_xor_sync(0xffffffffu, val, o);
        if (lane == 0) warp_sum[warp] = val;
        __syncthreads();
        if (j == 0) {
            float w = 0.f;
#pragma unroll
            for (int i = 0; i < 12; ++i) w += warp_sum[i];
            g_e[d] = expf(w - 384.0f);
        }
        __syncthreads();
    }
}

// ---------------------------------------------------------------------------
// Kernel 1: pre-round weights to tf32 (cvt.rna idempotent -> GEMM skips cvt)
// ---------------------------------------------------------------------------
__global__ void round_w_kernel(const float* __restrict__ Wv,
                               const float* __restrict__ Wo) {
    int i = blockIdx.x * blockDim.x + threadIdx.x;
    if (i >= KV * HIDDEN) return;
    g_wv[i] = to_tf32_f(Wv[i]);
    g_wo[i] = to_tf32_f(Wo[i]);
}

// ---------------------------------------------------------------------------
// Kernel 3: softmax == normalized 15-tap convolution along seq.
// Output written tf32-pre-rounded so gemm2 skips A-side cvt.
// ---------------------------------------------------------------------------
__global__ void smooth_kernel() {
    const int NC4 = KV / 4;
    int idx = blockIdx.x * blockDim.x + threadIdx.x;
    if (idx >= MTOT * NC4) return;
    int m = idx / NC4;
    int c = idx - m * NC4;
    int s = m & (SEQ - 1);

    const float4* vp = reinterpret_cast<const float4*>(g_v);
    float4 acc = vp[(size_t)m * NC4 + c];
    float z = 1.0f;
#pragma unroll
    for (int d = 1; d <= DMAX; ++d) {
        float e = g_e[d];
        if (s >= d) {
            float4 v = vp[(size_t)(m - d) * NC4 + c];
            acc.x += e * v.x; acc.y += e * v.y;
            acc.z += e * v.z; acc.w += e * v.w;
            z += e;
        }
        if (s + d < SEQ) {
            float4 v = vp[(size_t)(m + d) * NC4 + c];
            acc.x += e * v.x; acc.y += e * v.y;
            acc.z += e * v.z; acc.w += e * v.w;
            z += e;
        }
    }
    float inv = 1.0f / z;
    float4 o;
    o.x = to_tf32_f(acc.x * inv); o.y = to_tf32_f(acc.y * inv);
    o.z = to_tf32_f(acc.z * inv); o.w = to_tf32_f(acc.w * inv);
    reinterpret_cast<float4*>(g_a)[(size_t)m * NC4 + c] = o;
}

// ---------------------------------------------------------------------------
// Launch
// ---------------------------------------------------------------------------
extern "C" void kernel_launch(void* const* d_in, const int* in_sizes, int n_in,
                              void* d_out, int out_size) {
    const float* x  = (const float*)d_in[0];
    // d_in[1] = Wq, d_in[2] = Wk are dead (rope ignores its input)
    const float* Wv = (const float*)d_in[3];
    const float* Wo = (const float*)d_in[4];
    float* out = (float*)d_out;

    float* v_buf;  cudaGetSymbolAddress((void**)&v_buf, g_v);
    float* a_buf;  cudaGetSymbolAddress((void**)&a_buf, g_a);
    float* wv_buf; cudaGetSymbolAddress((void**)&wv_buf, g_wv);
    float* wo_buf; cudaGetSymbolAddress((void**)&wo_buf, g_wo);

    const int SMEM_BYTES = NSTAGE * STGB + 128;   // ~108 KB
    cudaFuncSetAttribute(gemm_tf32<true, false>,
                         cudaFuncAttributeMaxDynamicSharedMemorySize, SMEM_BYTES);
    cudaFuncSetAttribute(gemm_tf32<false, false>,
                         cudaFuncAttributeMaxDynamicSharedMemorySize, SMEM_BYTES);

    coeff_kernel<<<1, 384>>>();
    round_w_kernel<<<(KV * HIDDEN + 255) / 256, 256>>>(Wv, Wo);

    // 1) v = x @ Wv^T : [16384,768] x [256,768]  (A needs cvt, B pre-rounded)
    gemm_tf32<true, false><<<dim3(KV / 128, MTOT / 128), 256, SMEM_BYTES>>>(
        x, wv_buf, v_buf, MTOT, KV, HIDDEN);

    // 2) softmax(attn) @ v == normalized 15-tap convolution (tf32-rounded out)
    {
        int n = MTOT * (KV / 4);
        smooth_kernel<<<(n + 255) / 256, 256>>>();
    }

    // 3) out = a @ Wo^T : [16384,256] x [768,256]  (both pre-rounded: no cvt)
    gemm_tf32<false, false><<<dim3(HIDDEN / 128, MTOT / 128), 256, SMEM_BYTES>>>(
        a_buf, wo_buf, out, MTOT, HIDDEN, KV);
}

// round 9
// speedup vs baseline: 5.6585x; 1.0408x over previous
#include <cuda_runtime.h>
#include <math.h>
#include <stdint.h>

// Problem constants
#define SEQ     8192
#define BATCH   2
#define MTOT    (BATCH * SEQ)   // 16384
#define HIDDEN  768
#define KV      256
#define DMAX    7

// Scratch (static __device__ — no runtime allocation allowed)
__device__ float g_e[DMAX + 1];
__device__ __align__(16) float g_v[MTOT * KV];
__device__ __align__(16) float g_a[MTOT * KV];
__device__ __align__(16) float g_wv[KV * HIDDEN];   // tf32-pre-rounded Wv
__device__ __align__(16) float g_wo[HIDDEN * KV];   // tf32-pre-rounded Wo

// ---------------------------------------------------------------------------
// helpers
// ---------------------------------------------------------------------------
__device__ __forceinline__ uint32_t smem_u32(const void* p) {
    uint32_t a;
    asm("{ .reg .u64 t; cvta.to.shared.u64 t, %1; cvt.u32.u64 %0, t; }"
        : "=r"(a) : "l"(p));
    return a;
}

__device__ __forceinline__ uint32_t to_tf32_u(uint32_t x) {
    uint32_t u;
    asm("cvt.rna.tf32.f32 %0, %1;" : "=r"(u) : "f"(__uint_as_float(x)));
    return u;
}
__device__ __forceinline__ float to_tf32_f(float x) {
    uint32_t u;
    asm("cvt.rna.tf32.f32 %0, %1;" : "=r"(u) : "f"(x));
    return __uint_as_float(u);
}

__device__ __forceinline__ void ldsm4(uint32_t* r, uint32_t addr) {
    asm volatile("ldmatrix.sync.aligned.m8n8.x4.shared.b16 {%0,%1,%2,%3}, [%4];"
        : "=r"(r[0]), "=r"(r[1]), "=r"(r[2]), "=r"(r[3]) : "r"(addr));
}

__device__ __forceinline__ void mma_tf32(float* d, const uint32_t* a,
                                         const uint32_t* b) {
    asm volatile(
        "mma.sync.aligned.m16n8k8.row.col.f32.tf32.tf32.f32 "
        "{%0,%1,%2,%3}, {%4,%5,%6,%7}, {%8,%9}, {%0,%1,%2,%3};"
        : "+f"(d[0]), "+f"(d[1]), "+f"(d[2]), "+f"(d[3])
        : "r"(a[0]), "r"(a[1]), "r"(a[2]), "r"(a[3]), "r"(b[0]), "r"(b[1]));
}

#define CP_ASYNC16(dst, src) \
    asm volatile("cp.async.cg.shared.global [%0], [%1], 16;" \
                 :: "r"(dst), "l"(src) : "memory")
#define CP_COMMIT() asm volatile("cp.async.commit_group;" ::: "memory")
#define CP_WAIT1()  asm volatile("cp.async.wait_group 1;" ::: "memory")
#define CP_WAIT0()  asm volatile("cp.async.wait_group 0;" ::: "memory")

// SMEM geometry: rows padded to 36 floats (144B) -> conflict-free ldmatrix
#define ROWF   36
#define ATILE  (128 * ROWF * 4)            // 18432 B
#define STGB   (2 * ATILE)                 // A + B per stage = 36864 B
#define NSTAGE 3

// ---------------------------------------------------------------------------
// Single-pass TF32 tensor-core GEMM (NT): C[m,n] = sum_k A[m*K+k]*B[n*K+k]
// fp32 in/out, tf32 mma. CVT_A selects whether A fragments need tf32
// rounding (cvt.rna idempotent -> skipping it on pre-rounded data is
// bit-identical). When !CVT_A, A fragments are double-buffered across ks
// (register budget allows it without the CVT temps).
// 128x128 CTA tile, BK=32, 8 warps (2x4), warp tile 64x32, m16n8k8.
// 3-stage cp.async pipeline, ONE __syncthreads per chunk.
// ---------------------------------------------------------------------------
template <bool CVT_A>
__global__ __launch_bounds__(256, 2) void gemm_tf32(
    const float* __restrict__ A, const float* __restrict__ B,
    float* __restrict__ C, int M, int N, int K)
{
    extern __shared__ char dynsmem[];
    const uint32_t sb = (smem_u32(dynsmem) + 127u) & ~127u;

    const int tid  = threadIdx.x;
    const int wid  = tid >> 5;
    const int lane = tid & 31;
    const int bm   = blockIdx.y * 128;
    const int bn   = blockIdx.x * 128;
    const int NC   = K >> 5;

    const int warpM = (wid >> 2) * 64;   // 0 or 64
    const int warpN = (wid & 3) * 32;    // 0..96

    // cp.async mapping: thread -> (row 0..127, 16-float half of the 32 chunk)
    const int r = tid >> 1;
    const int h = tid & 1;
    const float* gA = A + (size_t)(bm + r) * K + h * 16;
    const float* gB = B + (size_t)(bn + r) * K + h * 16;
    const uint32_t sOffB = (uint32_t)(r * ROWF + h * 16) * 4u;

    float acc[4][4][4];
#pragma unroll
    for (int i = 0; i < 4; ++i)
#pragma unroll
        for (int j = 0; j < 4; ++j)
#pragma unroll
            for (int q = 0; q < 4; ++q) acc[i][j][q] = 0.f;

#define ISSUE_STAGE(stg, kt)                                              \
    do {                                                                  \
        uint32_t dA = sb + (uint32_t)(stg) * STGB + sOffB;                \
        uint32_t dB = dA + ATILE;                                         \
        const float* pa = gA + (kt);                                      \
        const float* pb = gB + (kt);                                      \
        CP_ASYNC16(dA,      pa);                                          \
        CP_ASYNC16(dA + 16, pa + 4);                                      \
        CP_ASYNC16(dA + 32, pa + 8);                                      \
        CP_ASYNC16(dA + 48, pa + 12);                                     \
        CP_ASYNC16(dB,      pb);                                          \
        CP_ASYNC16(dB + 16, pb + 4);                                      \
        CP_ASYNC16(dB + 32, pb + 8);                                      \
        CP_ASYNC16(dB + 48, pb + 12);                                     \
        CP_COMMIT();                                                      \
    } while (0)

    // prologue: stages 0 and 1 in flight
    ISSUE_STAGE(0, 0);
    ISSUE_STAGE(1, 32);

    // ldmatrix lane->address components (float offsets; x4 matrix = lane>>3)
    const uint32_t aOffF = (uint32_t)((warpM + (lane & 7) + 8 * ((lane >> 3) & 1))
                                      * ROWF + 4 * (lane >> 4));
    const uint32_t bOffF = (uint32_t)((warpN + ((lane >> 4) << 3) + (lane & 7))
                                      * ROWF + 4 * ((lane >> 3) & 1));

    int stage = 0;
    for (int c = 0; c < NC; ++c) {
        CP_WAIT1();
        __syncthreads();   // single barrier: data ready + prev chunk reads done

        if (c + 2 < NC) {
            int ns = stage + 2; if (ns >= NSTAGE) ns -= NSTAGE;
            ISSUE_STAGE(ns, (c + 2) * 32);
        }

        const uint32_t sA = sb + (uint32_t)stage * STGB + aOffF * 4u;
        const uint32_t sB = sb + (uint32_t)stage * STGB + ATILE + bOffF * 4u;

        if (CVT_A) {
            // single-buffer A (keeps regs low with CVT temps), B prefetched
            uint32_t bfr[2][2][4];
            ldsm4(bfr[0][0], sB);
            ldsm4(bfr[0][1], sB + 16u * ROWF * 4u);
#pragma unroll
            for (int ks = 0; ks < 4; ++ks) {
                const int cur = ks & 1;
                const uint32_t kb = (uint32_t)(ks * 8) * 4u;
                uint32_t af[4][4];
#pragma unroll
                for (int mt = 0; mt < 4; ++mt)
                    ldsm4(af[mt], sA + kb + (uint32_t)(mt * 16 * ROWF) * 4u);
                if (ks < 3) {
                    const uint32_t kn = (uint32_t)((ks + 1) * 8) * 4u;
                    ldsm4(bfr[cur ^ 1][0], sB + kn);
                    ldsm4(bfr[cur ^ 1][1], sB + kn + 16u * ROWF * 4u);
                }
#pragma unroll
                for (int mt = 0; mt < 4; ++mt) {
#pragma unroll
                    for (int q = 0; q < 4; ++q) af[mt][q] = to_tf32_u(af[mt][q]);
#pragma unroll
                    for (int nt = 0; nt < 4; ++nt)
                        mma_tf32(acc[mt][nt], af[mt],
                                 &bfr[cur][nt >> 1][(nt & 1) * 2]);
                }
            }
        } else {
            // full double-buffer of A and B fragments across ks
            uint32_t af[2][4][4], bfr[2][2][4];
#pragma unroll
            for (int mt = 0; mt < 4; ++mt)
                ldsm4(af[0][mt], sA + (uint32_t)(mt * 16 * ROWF) * 4u);
            ldsm4(bfr[0][0], sB);
            ldsm4(bfr[0][1], sB + 16u * ROWF * 4u);
#pragma unroll
            for (int ks = 0; ks < 4; ++ks) {
                const int cur = ks & 1;
                if (ks < 3) {
                    const uint32_t kn = (uint32_t)((ks + 1) * 8) * 4u;
#pragma unroll
                    for (int mt = 0; mt < 4; ++mt)
                        ldsm4(af[cur ^ 1][mt],
                              sA + kn + (uint32_t)(mt * 16 * ROWF) * 4u);
                    ldsm4(bfr[cur ^ 1][0], sB + kn);
                    ldsm4(bfr[cur ^ 1][1], sB + kn + 16u * ROWF * 4u);
                }
#pragma unroll
                for (int mt = 0; mt < 4; ++mt)
#pragma unroll
                    for (int nt = 0; nt < 4; ++nt)
                        mma_tf32(acc[mt][nt], af[cur][mt],
                                 &bfr[cur][nt >> 1][(nt & 1) * 2]);
            }
        }

        if (++stage >= NSTAGE) stage = 0;
    }
    CP_WAIT0();

    // epilogue: direct global stores (8B per lane per sub-tile row)
#pragma unroll
    for (int mt = 0; mt < 4; ++mt) {
#pragma unroll
        for (int nt = 0; nt < 4; ++nt) {
            int row = bm + warpM + mt * 16 + (lane >> 2);
            int col = bn + warpN + nt * 8 + (lane & 3) * 2;
            float2 v0 = make_float2(acc[mt][nt][0], acc[mt][nt][1]);
            float2 v1 = make_float2(acc[mt][nt][2], acc[mt][nt][3]);
            *reinterpret_cast<float2*>(C + (size_t)row * N + col) = v0;
            *reinterpret_cast<float2*>(C + (size_t)(row + 8) * N + col) = v1;
        }
    }
#undef ISSUE_STAGE
}

// ---------------------------------------------------------------------------
// Kernel 0: fused prologue.
// Block 0: softmax convolution coefficients (256-thread block reduce).
// Blocks 1..768: tf32 pre-rounding of Wv and Wo.
// ---------------------------------------------------------------------------
__global__ void pre_kernel(const float* __restrict__ Wv,
                           const float* __restrict__ Wo) {
    if (blockIdx.x == 0) {
        __shared__ float warp_sum[8];
        const int t = threadIdx.x;
        const int lane = t & 31, warp = t >> 5;
        const float cc = -logf(10000.0f) / 384.0f;
        for (int d = 0; d <= DMAX; ++d) {
            float val = 0.f;
            for (int j = t; j < 384; j += 256)
                val += cosf((float)d * __expf(cc * (float)j));
#pragma unroll
            for (int o = 16; o; o >>= 1)
                val += __shfl_xor_sync(0xffffffffu, val, o);
            if (lane == 0) warp_sum[warp] = val;
            __syncthreads();
            if (t == 0) {
                float w = 0.f;
#pragma unroll
                for (int i = 0; i < 8; ++i) w += warp_sum[i];
                g_e[d] = expf(w - 384.0f);
            }
            __syncthreads();
        }
    } else {
        int i = (blockIdx.x - 1) * 256 + threadIdx.x;   // covers KV*HIDDEN
        g_wv[i] = to_tf32_f(Wv[i]);
        g_wo[i] = to_tf32_f(Wo[i]);
    }
}

// ---------------------------------------------------------------------------
// Kernel 2: softmax == normalized 15-tap convolution along seq.
// Register sliding window: each thread produces 4 consecutive rows from one
// 18-row window (4.5 loads/output instead of 15). Z computed from boundary
// predicates. Output tf32-pre-rounded so gemm2 skips A-side cvt.
// ---------------------------------------------------------------------------
__global__ __launch_bounds__(256) void smooth_kernel() {
    const int NC4 = KV / 4;                       // 64
    int idx = blockIdx.x * blockDim.x + threadIdx.x;
    if (idx >= (MTOT / 4) * NC4) return;
    const int mg = idx >> 6;                      // 4-row group
    const int c  = idx & 63;
    const int m0 = mg << 2;
    const int s0 = m0 & (SEQ - 1);

    // coefficient taps e[|t-7|]
    float earr[15];
#pragma unroll
    for (int t = 0; t < 15; ++t) earr[t] = g_e[t < 7 ? 7 - t : t - 7];

    const float4* vp = reinterpret_cast<const float4*>(g_v);
    float4 w[18];
#pragma unroll
    for (int j = 0; j < 18; ++j) {
        int s = s0 - 7 + j;
        if (s >= 0 && s < SEQ)
            w[j] = vp[(size_t)(m0 - 7 + j) * NC4 + c];
        else
            w[j] = make_float4(0.f, 0.f, 0.f, 0.f);
    }

    float4* ap = reinterpret_cast<float4*>(g_a);
#pragma unroll
    for (int i = 0; i < 4; ++i) {
        const int s = s0 + i;
        float4 acc = make_float4(0.f, 0.f, 0.f, 0.f);
        float z = 1.0f;
#pragma unroll
        for (int t = 0; t < 15; ++t) {
            const float e = earr[t];
            const float4 vv = w[i + t];
            acc.x += e * vv.x; acc.y += e * vv.y;
            acc.z += e * vv.z; acc.w += e * vv.w;
        }
#pragma unroll
        for (int d = 1; d <= DMAX; ++d) {
            if (s >= d)       z += g_e[d];
            if (s + d < SEQ)  z += g_e[d];
        }
        const float inv = 1.0f / z;
        float4 o;
        o.x = to_tf32_f(acc.x * inv); o.y = to_tf32_f(acc.y * inv);
        o.z = to_tf32_f(acc.z * inv); o.w = to_tf32_f(acc.w * inv);
        ap[(size_t)(m0 + i) * NC4 + c] = o;
    }
}

// ---------------------------------------------------------------------------
// Launch
// ---------------------------------------------------------------------------
extern "C" void kernel_launch(void* const* d_in, const int* in_sizes, int n_in,
                              void* d_out, int out_size) {
    const float* x  = (const float*)d_in[0];
    // d_in[1] = Wq, d_in[2] = Wk are dead (rope ignores its input)
    const float* Wv = (const float*)d_in[3];
    const float* Wo = (const float*)d_in[4];
    float* out = (float*)d_out;

    float* v_buf;  cudaGetSymbolAddress((void**)&v_buf, g_v);
    float* a_buf;  cudaGetSymbolAddress((void**)&a_buf, g_a);
    float* wv_buf; cudaGetSymbolAddress((void**)&wv_buf, g_wv);
    float* wo_buf; cudaGetSymbolAddress((void**)&wo_buf, g_wo);

    const int SMEM_BYTES = NSTAGE * STGB + 128;   // ~108 KB
    cudaFuncSetAttribute(gemm_tf32<true>,
                         cudaFuncAttributeMaxDynamicSharedMemorySize, SMEM_BYTES);
    cudaFuncSetAttribute(gemm_tf32<false>,
                         cudaFuncAttributeMaxDynamicSharedMemorySize, SMEM_BYTES);

    // 0) coefficients + weight pre-rounding (one fused launch)
    pre_kernel<<<1 + KV * HIDDEN / 256, 256>>>(Wv, Wo);

    // 1) v = x @ Wv^T : [16384,768] x [256,768]  (A needs cvt, B pre-rounded)
    gemm_tf32<true><<<dim3(KV / 128, MTOT / 128), 256, SMEM_BYTES>>>(
        x, wv_buf, v_buf, MTOT, KV, HIDDEN);

    // 2) softmax(attn) @ v == normalized 15-tap convolution (tf32-rounded out)
    {
        int n = (MTOT / 4) * (KV / 4);
        smooth_kernel<<<(n + 255) / 256, 256>>>();
    }

    // 3) out = a @ Wo^T : [16384,256] x [768,256]  (both pre-rounded: no cvt)
    gemm_tf32<false><<<dim3(HIDDEN / 128, MTOT / 128), 256, SMEM_BYTES>>>(
        a_buf, wo_buf, out, MTOT, HIDDEN, KV);
}

// round 10
// speedup vs baseline: 6.1537x; 1.0875x over previous
#include <cuda_runtime.h>
#include <math.h>
#include <stdint.h>

// Problem constants
#define SEQ     8192
#define BATCH   2
#define MTOT    (BATCH * SEQ)   // 16384
#define HIDDEN  768
#define KV      256
#define DMAX    7

// Scratch (static __device__ — no runtime allocation allowed)
__device__ float g_e[DMAX + 1];
__device__ __align__(16) float g_v[MTOT * KV];
__device__ __align__(16) float g_a[MTOT * KV];
__device__ __align__(16) float g_wv[KV * HIDDEN];   // tf32-pre-rounded Wv
__device__ __align__(16) float g_wo[HIDDEN * KV];   // tf32-pre-rounded Wo

// ---------------------------------------------------------------------------
// helpers
// ---------------------------------------------------------------------------
__device__ __forceinline__ uint32_t smem_u32(const void* p) {
    uint32_t a;
    asm("{ .reg .u64 t; cvta.to.shared.u64 t, %1; cvt.u32.u64 %0, t; }"
        : "=r"(a) : "l"(p));
    return a;
}

__device__ __forceinline__ uint32_t to_tf32_u(uint32_t x) {
    uint32_t u;
    asm("cvt.rna.tf32.f32 %0, %1;" : "=r"(u) : "f"(__uint_as_float(x)));
    return u;
}
__device__ __forceinline__ float to_tf32_f(float x) {
    uint32_t u;
    asm("cvt.rna.tf32.f32 %0, %1;" : "=r"(u) : "f"(x));
    return __uint_as_float(u);
}

__device__ __forceinline__ void ldsm4(uint32_t* r, uint32_t addr) {
    asm volatile("ldmatrix.sync.aligned.m8n8.x4.shared.b16 {%0,%1,%2,%3}, [%4];"
        : "=r"(r[0]), "=r"(r[1]), "=r"(r[2]), "=r"(r[3]) : "r"(addr));
}

__device__ __forceinline__ void mma_tf32(float* d, const uint32_t* a,
                                         const uint32_t* b) {
    asm volatile(
        "mma.sync.aligned.m16n8k8.row.col.f32.tf32.tf32.f32 "
        "{%0,%1,%2,%3}, {%4,%5,%6,%7}, {%8,%9}, {%0,%1,%2,%3};"
        : "+f"(d[0]), "+f"(d[1]), "+f"(d[2]), "+f"(d[3])
        : "r"(a[0]), "r"(a[1]), "r"(a[2]), "r"(a[3]), "r"(b[0]), "r"(b[1]));
}

#define CP_ASYNC16(dst, src) \
    asm volatile("cp.async.cg.shared.global [%0], [%1], 16;" \
                 :: "r"(dst), "l"(src) : "memory")
#define CP_COMMIT() asm volatile("cp.async.commit_group;" ::: "memory")
#define CP_WAIT2()  asm volatile("cp.async.wait_group 2;" ::: "memory")
#define CP_WAIT0()  asm volatile("cp.async.wait_group 0;" ::: "memory")

// SMEM geometry: rows padded to 36 floats (144B) -> conflict-free ldmatrix
#define ROWF    36
#define ASZ     (256 * ROWF * 4)           // A tile bytes: 36864
#define BSZ     (128 * ROWF * 4)           // B tile bytes: 18432
#define STGB    (ASZ + BSZ)                // 55296 per stage
#define NSTAGE  4                          // 4 stages = 216 KB

// ---------------------------------------------------------------------------
// Single-pass TF32 tensor-core GEMM (NT): C[m,n] = sum_k A[m*K+k]*B[n*K+k]
// fp32 in/out, tf32 mma. CVT_A selects whether A fragments need rounding
// (cvt.rna idempotent -> skipping on pre-rounded data is bit-identical).
// CTA tile 256x128, 512 threads (16 warps, 4x4), warp tile 64x32, m16n8k8.
// 4-stage cp.async pipeline (prefetch distance 3), ONE __syncthreads/chunk,
// fragment double-buffering across ks.
// M multiple of 256, N multiple of 128, K multiple of 32.
// ---------------------------------------------------------------------------
template <bool CVT_A>
__global__ __launch_bounds__(512, 1) void gemm_tf32(
    const float* __restrict__ A, const float* __restrict__ B,
    float* __restrict__ C, int M, int N, int K)
{
    extern __shared__ char dynsmem[];
    const uint32_t sb = (smem_u32(dynsmem) + 127u) & ~127u;

    const int tid  = threadIdx.x;
    const int wid  = tid >> 5;
    const int lane = tid & 31;
    const int bm   = blockIdx.y * 256;
    const int bn   = blockIdx.x * 128;
    const int NC   = K >> 5;

    const int warpM = (wid >> 2) * 64;   // 0,64,128,192
    const int warpN = (wid & 3) * 32;    // 0..96

    // cp.async mapping
    // A: thread -> (row 0..255, 16-float half); 4x16B each
    const int ra = tid >> 1;
    const int ha = tid & 1;
    const float* gA = A + (size_t)(bm + ra) * K + ha * 16;
    const uint32_t sOffA = (uint32_t)(ra * ROWF + ha * 16) * 4u;
    // B: thread -> (row 0..127, 8-float quarter); 2x16B each
    const int rb = tid >> 2;
    const int hb = tid & 3;
    const float* gB = B + (size_t)(bn + rb) * K + hb * 8;
    const uint32_t sOffB = (uint32_t)(rb * ROWF + hb * 8) * 4u;

    float acc[4][4][4];
#pragma unroll
    for (int i = 0; i < 4; ++i)
#pragma unroll
        for (int j = 0; j < 4; ++j)
#pragma unroll
            for (int q = 0; q < 4; ++q) acc[i][j][q] = 0.f;

#define ISSUE_STAGE(stg, kt)                                              \
    do {                                                                  \
        uint32_t dA = sb + (uint32_t)(stg) * STGB + sOffA;                \
        uint32_t dB = sb + (uint32_t)(stg) * STGB + ASZ + sOffB;          \
        const float* pa = gA + (kt);                                      \
        const float* pb = gB + (kt);                                      \
        CP_ASYNC16(dA,      pa);                                          \
        CP_ASYNC16(dA + 16, pa + 4);                                      \
        CP_ASYNC16(dA + 32, pa + 8);                                      \
        CP_ASYNC16(dA + 48, pa + 12);                                     \
        CP_ASYNC16(dB,      pb);                                          \
        CP_ASYNC16(dB + 16, pb + 4);                                      \
        CP_COMMIT();                                                      \
    } while (0)

    // prologue: stages 0..2 in flight
    ISSUE_STAGE(0, 0);
    ISSUE_STAGE(1, 32);
    ISSUE_STAGE(2, 64);

    // ldmatrix lane->address components (float offsets; x4 matrix = lane>>3)
    const uint32_t aOffF = (uint32_t)((warpM + (lane & 7) + 8 * ((lane >> 3) & 1))
                                      * ROWF + 4 * (lane >> 4));
    const uint32_t bOffF = (uint32_t)((warpN + ((lane >> 4) << 3) + (lane & 7))
                                      * ROWF + 4 * ((lane >> 3) & 1));

    int stage = 0;
    for (int c = 0; c < NC; ++c) {
        CP_WAIT2();
        __syncthreads();   // data ready + prev chunk reads complete

        if (c + 3 < NC) {
            int ns = stage + 3; if (ns >= NSTAGE) ns -= NSTAGE;
            ISSUE_STAGE(ns, (c + 3) * 32);
        }

        const uint32_t sA = sb + (uint32_t)stage * STGB + aOffF * 4u;
        const uint32_t sB = sb + (uint32_t)stage * STGB + ASZ + bOffF * 4u;

        if (CVT_A) {
            // single-buffer A (CVT temps), B double-buffered
            uint32_t bfr[2][2][4];
            ldsm4(bfr[0][0], sB);
            ldsm4(bfr[0][1], sB + 16u * ROWF * 4u);
#pragma unroll
            for (int ks = 0; ks < 4; ++ks) {
                const int cur = ks & 1;
                const uint32_t kb = (uint32_t)(ks * 8) * 4u;
                uint32_t af[4][4];
#pragma unroll
                for (int mt = 0; mt < 4; ++mt)
                    ldsm4(af[mt], sA + kb + (uint32_t)(mt * 16 * ROWF) * 4u);
                if (ks < 3) {
                    const uint32_t kn = (uint32_t)((ks + 1) * 8) * 4u;
                    ldsm4(bfr[cur ^ 1][0], sB + kn);
                    ldsm4(bfr[cur ^ 1][1], sB + kn + 16u * ROWF * 4u);
                }
#pragma unroll
                for (int mt = 0; mt < 4; ++mt) {
#pragma unroll
                    for (int q = 0; q < 4; ++q) af[mt][q] = to_tf32_u(af[mt][q]);
#pragma unroll
                    for (int nt = 0; nt < 4; ++nt)
                        mma_tf32(acc[mt][nt], af[mt],
                                 &bfr[cur][nt >> 1][(nt & 1) * 2]);
                }
            }
        } else {
            // full double-buffer of A and B fragments across ks
            uint32_t af[2][4][4], bfr[2][2][4];
#pragma unroll
            for (int mt = 0; mt < 4; ++mt)
                ldsm4(af[0][mt], sA + (uint32_t)(mt * 16 * ROWF) * 4u);
            ldsm4(bfr[0][0], sB);
            ldsm4(bfr[0][1], sB + 16u * ROWF * 4u);
#pragma unroll
            for (int ks = 0; ks < 4; ++ks) {
                const int cur = ks & 1;
                if (ks < 3) {
                    const uint32_t kn = (uint32_t)((ks + 1) * 8) * 4u;
#pragma unroll
                    for (int mt = 0; mt < 4; ++mt)
                        ldsm4(af[cur ^ 1][mt],
                              sA + kn + (uint32_t)(mt * 16 * ROWF) * 4u);
                    ldsm4(bfr[cur ^ 1][0], sB + kn);
                    ldsm4(bfr[cur ^ 1][1], sB + kn + 16u * ROWF * 4u);
                }
#pragma unroll
                for (int mt = 0; mt < 4; ++mt)
#pragma unroll
                    for (int nt = 0; nt < 4; ++nt)
                        mma_tf32(acc[mt][nt], af[cur][mt],
                                 &bfr[cur][nt >> 1][(nt & 1) * 2]);
            }
        }

        if (++stage >= NSTAGE) stage = 0;
    }
    CP_WAIT0();

    // epilogue: direct global stores (8B per lane per sub-tile row)
#pragma unroll
    for (int mt = 0; mt < 4; ++mt) {
#pragma unroll
        for (int nt = 0; nt < 4; ++nt) {
            int row = bm + warpM + mt * 16 + (lane >> 2);
            int col = bn + warpN + nt * 8 + (lane & 3) * 2;
            float2 v0 = make_float2(acc[mt][nt][0], acc[mt][nt][1]);
            float2 v1 = make_float2(acc[mt][nt][2], acc[mt][nt][3]);
            *reinterpret_cast<float2*>(C + (size_t)row * N + col) = v0;
            *reinterpret_cast<float2*>(C + (size_t)(row + 8) * N + col) = v1;
        }
    }
#undef ISSUE_STAGE
}

// ---------------------------------------------------------------------------
// Kernel 0: fused prologue.
// Block 0: softmax convolution coefficients (256-thread block reduce).
// Blocks 1..768: tf32 pre-rounding of Wv and Wo.
// ---------------------------------------------------------------------------
__global__ void pre_kernel(const float* __restrict__ Wv,
                           const float* __restrict__ Wo) {
    if (blockIdx.x == 0) {
        __shared__ float warp_sum[8];
        const int t = threadIdx.x;
        const int lane = t & 31, warp = t >> 5;
        const float cc = -logf(10000.0f) / 384.0f;
        for (int d = 0; d <= DMAX; ++d) {
            float val = 0.f;
            for (int j = t; j < 384; j += 256)
                val += cosf((float)d * __expf(cc * (float)j));
#pragma unroll
            for (int o = 16; o; o >>= 1)
                val += __shfl_xor_sync(0xffffffffu, val, o);
            if (lane == 0) warp_sum[warp] = val;
            __syncthreads();
            if (t == 0) {
                float w = 0.f;
#pragma unroll
                for (int i = 0; i < 8; ++i) w += warp_sum[i];
                g_e[d] = expf(w - 384.0f);
            }
            __syncthreads();
        }
    } else {
        int i = (blockIdx.x - 1) * 256 + threadIdx.x;   // covers KV*HIDDEN
        g_wv[i] = to_tf32_f(Wv[i]);
        g_wo[i] = to_tf32_f(Wo[i]);
    }
}

// ---------------------------------------------------------------------------
// Kernel 2: softmax == normalized 15-tap convolution along seq.
// Register sliding window: each thread produces 4 consecutive rows from one
// 18-row window. Output tf32-pre-rounded so gemm2 skips A-side cvt.
// ---------------------------------------------------------------------------
__global__ __launch_bounds__(256) void smooth_kernel() {
    const int NC4 = KV / 4;                       // 64
    int idx = blockIdx.x * blockDim.x + threadIdx.x;
    if (idx >= (MTOT / 4) * NC4) return;
    const int mg = idx >> 6;                      // 4-row group
    const int c  = idx & 63;
    const int m0 = mg << 2;
    const int s0 = m0 & (SEQ - 1);

    float earr[15];
#pragma unroll
    for (int t = 0; t < 15; ++t) earr[t] = g_e[t < 7 ? 7 - t : t - 7];

    const float4* vp = reinterpret_cast<const float4*>(g_v);
    float4 w[18];
#pragma unroll
    for (int j = 0; j < 18; ++j) {
        int s = s0 - 7 + j;
        if (s >= 0 && s < SEQ)
            w[j] = vp[(size_t)(m0 - 7 + j) * NC4 + c];
        else
            w[j] = make_float4(0.f, 0.f, 0.f, 0.f);
    }

    float4* ap = reinterpret_cast<float4*>(g_a);
#pragma unroll
    for (int i = 0; i < 4; ++i) {
        const int s = s0 + i;
        float4 acc = make_float4(0.f, 0.f, 0.f, 0.f);
        float z = 1.0f;
#pragma unroll
        for (int t = 0; t < 15; ++t) {
            const float e = earr[t];
            const float4 vv = w[i + t];
            acc.x += e * vv.x; acc.y += e * vv.y;
            acc.z += e * vv.z; acc.w += e * vv.w;
        }
#pragma unroll
        for (int d = 1; d <= DMAX; ++d) {
            if (s >= d)       z += g_e[d];
            if (s + d < SEQ)  z += g_e[d];
        }
        const float inv = 1.0f / z;
        float4 o;
        o.x = to_tf32_f(acc.x * inv); o.y = to_tf32_f(acc.y * inv);
        o.z = to_tf32_f(acc.z * inv); o.w = to_tf32_f(acc.w * inv);
        ap[(size_t)(m0 + i) * NC4 + c] = o;
    }
}

// ---------------------------------------------------------------------------
// Launch
// ---------------------------------------------------------------------------
extern "C" void kernel_launch(void* const* d_in, const int* in_sizes, int n_in,
                              void* d_out, int out_size) {
    const float* x  = (const float*)d_in[0];
    // d_in[1] = Wq, d_in[2] = Wk are dead (rope ignores its input)
    const float* Wv = (const float*)d_in[3];
    const float* Wo = (const float*)d_in[4];
    float* out = (float*)d_out;

    float* v_buf;  cudaGetSymbolAddress((void**)&v_buf, g_v);
    float* a_buf;  cudaGetSymbolAddress((void**)&a_buf, g_a);
    float* wv_buf; cudaGetSymbolAddress((void**)&wv_buf, g_wv);
    float* wo_buf; cudaGetSymbolAddress((void**)&wo_buf, g_wo);

    const int SMEM_BYTES = NSTAGE * STGB + 128;   // ~216 KB
    cudaFuncSetAttribute(gemm_tf32<true>,
                         cudaFuncAttributeMaxDynamicSharedMemorySize, SMEM_BYTES);
    cudaFuncSetAttribute(gemm_tf32<false>,
                         cudaFuncAttributeMaxDynamicSharedMemorySize, SMEM_BYTES);

    // 0) coefficients + weight pre-rounding (one fused launch)
    pre_kernel<<<1 + KV * HIDDEN / 256, 256>>>(Wv, Wo);

    // 1) v = x @ Wv^T : [16384,768] x [256,768]  (A needs cvt, B pre-rounded)
    gemm_tf32<true><<<dim3(KV / 128, MTOT / 256), 512, SMEM_BYTES>>>(
        x, wv_buf, v_buf, MTOT, KV, HIDDEN);

    // 2) softmax(attn) @ v == normalized 15-tap convolution (tf32-rounded out)
    {
        int n = (MTOT / 4) * (KV / 4);
        smooth_kernel<<<(n + 255) / 256, 256>>>();
    }

    // 3) out = a @ Wo^T : [16384,256] x [768,256]  (both pre-rounded: no cvt)
    gemm_tf32<false><<<dim3(HIDDEN / 128, MTOT / 256), 512, SMEM_BYTES>>>(
        a_buf, wo_buf, out, MTOT, HIDDEN, KV);
}